// round 5
// baseline (speedup 1.0000x reference)
#include <cuda_runtime.h>

#define QSCALE 0.17677669529663687f   // 32^-0.5

typedef unsigned long long u64;
typedef unsigned int u32;

// ---------------------------------------------------------------------------
// Scratch (static device arrays; no allocation allowed)
// ---------------------------------------------------------------------------
__device__ __align__(16) float g_wt [1152 * 1024];        // K-major weights [k][co]
__device__ __align__(16) float g_q  [32 * 1024 * 32];     // [bh][pos][d] (scaled)
__device__ __align__(16) float g_k  [32 * 1024 * 32];
__device__ __align__(16) float g_v  [32 * 1024 * 32];
__device__ __align__(16) float g_rx [32 * 1024 * 32];     // [bh][i][jc]
__device__ __align__(16) float g_ry [32 * 1024 * 32];     // [bh][i][jr]
__device__ __align__(16) float g_att[4 * 256 * 1024];     // scrambled-channel att
__device__ __align__(16) float4 g_kf[32 * 128 * 4 * 32];  // split-tf32 K frags (8MB)
__device__ __align__(16) float2 g_vf[32 * 128 * 4 * 32];  // tf32 V frags (4MB)

// ---------------------------------------------------------------------------
// f32x2 packed helpers (conv path)
// ---------------------------------------------------------------------------
__device__ __forceinline__ u64 pk2(float lo, float hi) {
    u64 r; asm("mov.b64 %0,{%1,%2};" : "=l"(r) : "f"(lo), "f"(hi)); return r;
}
__device__ __forceinline__ void upk2(float& lo, float& hi, u64 v) {
    asm("mov.b64 {%0,%1},%2;" : "=f"(lo), "=f"(hi) : "l"(v));
}
__device__ __forceinline__ void ffma2(u64& d, u64 a, u64 b) {
    asm("fma.rn.f32x2 %0,%1,%2,%0;" : "+l"(d) : "l"(a), "l"(b));
}

// ---------------------------------------------------------------------------
// tf32 helpers (attention path)
// ---------------------------------------------------------------------------
__device__ __forceinline__ u32 tf32_of(float f) {
    u32 r; asm("cvt.rna.tf32.f32 %0,%1;" : "=r"(r) : "f"(f)); return r;
}
__device__ __forceinline__ void tf32_split(float v, u32& h, u32& l) {
    h = tf32_of(v);
    l = tf32_of(v - __uint_as_float(h));
}
#define MMA_TF32(d0,d1,d2,d3,a0,a1,a2,a3,b0,b1)                               \
    asm("mma.sync.aligned.m16n8k8.row.col.f32.tf32.tf32.f32 "                  \
        "{%0,%1,%2,%3},{%4,%5,%6,%7},{%8,%9},{%0,%1,%2,%3};"                   \
        : "+f"(d0), "+f"(d1), "+f"(d2), "+f"(d3)                               \
        : "r"(a0), "r"(a1), "r"(a2), "r"(a3), "r"(b0), "r"(b1))

// ---------------------------------------------------------------------------
// K0: tiled coalesced transpose -> K-major [k][co]
// ---------------------------------------------------------------------------
__global__ __launch_bounds__(256) void k_wt(const float* __restrict__ cw,
                                            const float* __restrict__ qw) {
    __shared__ float T[32][33];
    const int tx = threadIdx.x & 31, ty = threadIdx.x >> 5;
    const int k0 = blockIdx.x * 32, c0 = blockIdx.y * 32;
#pragma unroll
    for (int r = 0; r < 4; r++) {
        int co = c0 + ty + r * 8;
        const float* src = (co < 256) ? cw + (size_t)co * 1152
                                      : qw + (size_t)(co - 256) * 1152;
        T[ty + r * 8][tx] = src[k0 + tx];
    }
    __syncthreads();
#pragma unroll
    for (int r = 0; r < 4; r++) {
        int k = k0 + ty + r * 8;
        g_wt[(size_t)k * 1024 + c0 + tx] = T[tx][ty + r * 8];
    }
}

// ---------------------------------------------------------------------------
// K1: fused 3x3 conv. Block: 128 co x 64 pos (2 rows). 256 thr, tile 8co x 4pos.
// ---------------------------------------------------------------------------
__global__ __launch_bounds__(256) void k_conv(const float* __restrict__ x,
                                              const float* __restrict__ cb,
                                              const float* __restrict__ qb,
                                              float* __restrict__ out) {
    __shared__ __align__(16) float Ws[72 * 128];
    __shared__ float Xs[8 * 4 * 37];

    const int tid = threadIdx.x;
    const int b   = blockIdx.x >> 4;
    const int y0  = (blockIdx.x & 15) << 1;
    const int co_base = blockIdx.y << 7;
    const int cg = tid >> 4, pg = tid & 15;
    const int ly = pg >> 3, lx0 = (pg & 7) << 2;
    const int co0 = co_base + cg * 8;

    u64 acc[4][4];
#pragma unroll
    for (int a = 0; a < 4; a++)
#pragma unroll
        for (int c = 0; c < 4; c++) acc[a][c] = 0ULL;

    for (int ch = 0; ch < 16; ch++) {
        const int ci0 = ch << 3;
        __syncthreads();
        for (int t = tid; t < 72 * 32; t += 256) {
            int row = t >> 5, f = t & 31;
            *(float4*)&Ws[row * 128 + f * 4] =
                *(const float4*)&g_wt[(size_t)(ci0 * 9 + row) * 1024 + co_base + f * 4];
        }
        for (int t = tid; t < 1184; t += 256) {
            int ci  = t / 148;
            int rem = t - ci * 148;
            int rr  = rem / 37;
            int c   = rem - rr * 37;
            int gy = y0 - 1 + rr;
            int gx = c - 1;
            float v = 0.f;
            if (gy >= 0 && gy < 32 && (unsigned)gx < 32u)
                v = x[(size_t)((b * 128 + ci0 + ci) * 32 + gy) * 32 + gx];
            Xs[t] = v;
        }
        __syncthreads();
#pragma unroll
        for (int ci = 0; ci < 8; ci++) {
#pragma unroll
            for (int ky = 0; ky < 3; ky++) {
                const float* xp = Xs + ci * 148 + (ly + ky) * 37 + lx0;
                u64 xb[6];
#pragma unroll
                for (int t = 0; t < 6; t++) { float xv = xp[t]; xb[t] = pk2(xv, xv); }
#pragma unroll
                for (int kx = 0; kx < 3; kx++) {
                    const ulonglong2* wp =
                        (const ulonglong2*)(Ws + (ci * 9 + ky * 3 + kx) * 128 + cg * 8);
                    ulonglong2 wA = wp[0], wB = wp[1];
#pragma unroll
                    for (int c = 0; c < 4; c++) {
                        ffma2(acc[0][c], wA.x, xb[kx + c]);
                        ffma2(acc[1][c], wA.y, xb[kx + c]);
                        ffma2(acc[2][c], wB.x, xb[kx + c]);
                        ffma2(acc[3][c], wB.y, xb[kx + c]);
                    }
                }
            }
        }
    }

    float bias[8];
    const float* bsrc = (co0 < 256) ? (cb + co0) : (qb + co0 - 256);
#pragma unroll
    for (int t = 0; t < 8; t++) bias[t] = bsrc[t];

    float v[8][4];
#pragma unroll
    for (int a = 0; a < 4; a++)
#pragma unroll
        for (int c = 0; c < 4; c++) {
            float lo, hi; upk2(lo, hi, acc[a][c]);
            v[2 * a][c]     = lo + bias[2 * a];
            v[2 * a + 1][c] = hi + bias[2 * a + 1];
        }

    const int base_pos = (y0 + ly) * 32 + lx0;
    if (co0 < 256) {
#pragma unroll
        for (int cc = 0; cc < 8; cc++)
            *(float4*)&out[(size_t)(b * 512 + co0 + cc) * 1024 + base_pos] =
                make_float4(v[cc][0], v[cc][1], v[cc][2], v[cc][3]);
    } else {
        int qc0 = co0 - 256;
        int seg = qc0 >> 8;              // 0=q 1=k 2=v
        int c8  = qc0 & 255;
        int h = c8 >> 5, d0 = c8 & 31;
        float* dstb = (seg == 0 ? g_q : (seg == 1 ? g_k : g_v))
                      + (size_t)((b * 8 + h) * 1024) * 32 + d0;
        float scale = (seg == 0) ? QSCALE : 1.f;
#pragma unroll
        for (int c = 0; c < 4; c++) {
            int pos = base_pos + c;
            *(float4*)(dstb + (size_t)pos * 32) =
                make_float4(v[0][c] * scale, v[1][c] * scale, v[2][c] * scale, v[3][c] * scale);
            *(float4*)(dstb + (size_t)pos * 32 + 4) =
                make_float4(v[4][c] * scale, v[5][c] * scale, v[6][c] * scale, v[7][c] * scale);
        }
    }
}

// ---------------------------------------------------------------------------
// K2: rel-logit tables.
// ---------------------------------------------------------------------------
__global__ __launch_bounds__(256) void k_rel(const float* __restrict__ krx,
                                             const float* __restrict__ kry) {
    __shared__ float KX[63 * 33], KY[63 * 33], QR[32 * 32], QT[32 * 32];
    const int bh = blockIdx.x, qg = blockIdx.y, tid = threadIdx.x;

    for (int t = tid; t < 63 * 32; t += 256) {
        int m = t >> 5, d = t & 31;
        KX[m * 33 + d] = krx[t];
        KY[m * 33 + d] = kry[t];
    }
    for (int t = tid; t < 1024; t += 256) {
        int il = t >> 5, d = t & 31;
        QR[t] = g_q[(size_t)(bh * 1024 + qg * 32 + il) * 32 + d];
        QT[t] = g_q[(size_t)(bh * 1024 + il * 32 + qg) * 32 + d];
    }
    __syncthreads();

    const int wid = tid >> 5, j = tid & 31;
#pragma unroll
    for (int r = 0; r < 4; r++) {
        int il = r * 8 + wid;
        int m = j - il + 31;
        float ax = 0.f, ay = 0.f;
#pragma unroll
        for (int d = 0; d < 32; d++) {
            ax += QR[il * 32 + d] * KX[m * 33 + d];
            ay += QT[il * 32 + d] * KY[m * 33 + d];
        }
        int i = qg * 32 + il;
        g_rx[(size_t)(bh * 1024 + i) * 32 + j] = ax;
        g_ry[(size_t)(bh * 1024 + i) * 32 + j] = ay;
    }
}

// ---------------------------------------------------------------------------
// K2b: fragment prep — split-tf32 K frags + tf32 V frags in MMA lane order.
//   g_kf[((bh*128+nt)*4+s)*32+lane] = (hi,lo of K[nt*8+gid][s*8+tig], d+4)
//   g_vf[((bh*128+kt)*4+dt)*32+lane] = tf32(V[kt*8+tig][dt*8+gid], row+4)
// Grid (32 bh, 8 chunks of 128 keys), 256 thr.
// ---------------------------------------------------------------------------
__global__ __launch_bounds__(256) void k_prep() {
    __shared__ float Ksm[128 * 33], Vsm[128 * 33];
    const int bh = blockIdx.x, c = blockIdx.y, tid = threadIdx.x;
    const int j0 = c * 128;

    for (int t = tid; t < 1024; t += 256) {
        int r = t >> 3, f = (t & 7) * 4;
        float4 kv = *(const float4*)&g_k[(size_t)(bh * 1024 + j0 + r) * 32 + f];
        Ksm[r * 33 + f] = kv.x; Ksm[r * 33 + f + 1] = kv.y;
        Ksm[r * 33 + f + 2] = kv.z; Ksm[r * 33 + f + 3] = kv.w;
        float4 vv = *(const float4*)&g_v[(size_t)(bh * 1024 + j0 + r) * 32 + f];
        Vsm[r * 33 + f] = vv.x; Vsm[r * 33 + f + 1] = vv.y;
        Vsm[r * 33 + f + 2] = vv.z; Vsm[r * 33 + f + 3] = vv.w;
    }
    __syncthreads();

    for (int t = tid; t < 2048; t += 256) {
        int lane = t & 31, s = (t >> 5) & 3, ntl = t >> 7;
        int gid = lane >> 2, tig = lane & 3;
        int j = ntl * 8 + gid;
        u32 h0, l0, h1, l1;
        tf32_split(Ksm[j * 33 + s * 8 + tig],     h0, l0);
        tf32_split(Ksm[j * 33 + s * 8 + tig + 4], h1, l1);
        g_kf[(size_t)((bh * 128 + c * 16 + ntl) * 4 + s) * 32 + lane] =
            make_float4(__uint_as_float(h0), __uint_as_float(l0),
                        __uint_as_float(h1), __uint_as_float(l1));
    }
    for (int t = tid; t < 2048; t += 256) {
        int lane = t & 31, dt = (t >> 5) & 3, ktl = t >> 7;
        int gid = lane >> 2, tig = lane & 3;
        u32 b0 = tf32_of(Vsm[(ktl * 8 + tig) * 33 + dt * 8 + gid]);
        u32 b1 = tf32_of(Vsm[(ktl * 8 + tig + 4) * 33 + dt * 8 + gid]);
        g_vf[(size_t)((bh * 128 + c * 16 + ktl) * 4 + dt) * 32 + lane] =
            make_float2(__uint_as_float(b0), __uint_as_float(b1));
    }
}

// ---------------------------------------------------------------------------
// K3: register-flash tensor-core attention.
// Grid (32 bh, 8), block 128 thr = 4 warps; warp owns 32 queries (m32),
// streams 1024 keys in 8-key tiles. Online softmax in registers.
// ---------------------------------------------------------------------------
__global__ __launch_bounds__(128) void k_attn() {
    __shared__ float RXs[128 * 33], RYs[128 * 33];

    const int bh = blockIdx.x, qt = blockIdx.y;
    const int tid = threadIdx.x, w = tid >> 5, lane = tid & 31;
    const int gid = lane >> 2, tig = lane & 3;
    const int qb = qt * 128;                  // block's global q base within bh
    const int lq0 = w * 32;                   // warp's block-local q base
    const size_t qbase = (size_t)bh * 1024 * 32;

    // stage rel tables for block's 128 queries
    for (int t = tid; t < 128 * 32; t += 128) {
        int r = t >> 5, cc = t & 31;
        RXs[r * 33 + cc] = g_rx[(size_t)(bh * 1024 + qb + r) * 32 + cc];
        RYs[r * 33 + cc] = g_ry[(size_t)(bh * 1024 + qb + r) * 32 + cc];
    }

    // Q fragments (split tf32): rows qb+lq0+mt*16+gid (+8), cols s*8+tig (+4)
    u32 qh[2][4][4], ql[2][4][4];
#pragma unroll
    for (int mt = 0; mt < 2; mt++)
#pragma unroll
        for (int s = 0; s < 4; s++) {
            int r0 = qb + lq0 + mt * 16 + gid, r1 = r0 + 8;
            int c0 = s * 8 + tig, c1 = c0 + 4;
            tf32_split(g_q[qbase + (size_t)r0 * 32 + c0], qh[mt][s][0], ql[mt][s][0]);
            tf32_split(g_q[qbase + (size_t)r1 * 32 + c0], qh[mt][s][1], ql[mt][s][1]);
            tf32_split(g_q[qbase + (size_t)r0 * 32 + c1], qh[mt][s][2], ql[mt][s][2]);
            tf32_split(g_q[qbase + (size_t)r1 * 32 + c1], qh[mt][s][3], ql[mt][s][3]);
        }
    __syncthreads();

    // rows handled by this lane: rr = mt*2 + half -> local q = lq0+mt*16+gid+half*8
    int lr[4];
#pragma unroll
    for (int rr = 0; rr < 4; rr++) lr[rr] = lq0 + (rr >> 1) * 16 + gid + (rr & 1) * 8;

    // rel_x registers: (8*k + 2tig (+1)) pattern, period 4 in nt
    float rxe[4][4], rxo[4][4];
#pragma unroll
    for (int rr = 0; rr < 4; rr++)
#pragma unroll
        for (int k = 0; k < 4; k++) {
            rxe[rr][k] = RXs[lr[rr] * 33 + 8 * k + 2 * tig];
            rxo[rr][k] = RXs[lr[rr] * 33 + 8 * k + 2 * tig + 1];
        }

    float m[4] = {-1e30f, -1e30f, -1e30f, -1e30f};
    float l[4] = {0.f, 0.f, 0.f, 0.f};
    float o[2][4][4];
#pragma unroll
    for (int mt = 0; mt < 2; mt++)
#pragma unroll
        for (int dt = 0; dt < 4; dt++)
#pragma unroll
            for (int r = 0; r < 4; r++) o[mt][dt][r] = 0.f;

    const float4* kf = g_kf + (size_t)bh * 16384 + lane;
    const float2* vf = g_vf + (size_t)bh * 16384 + lane;
    const int srcA = (lane & ~3) | (tig >> 1);
    const int srcB = srcA + 2;
    const int sel  = tig & 1;

    for (int nt4 = 0; nt4 < 32; nt4++) {
        float ry[4];
#pragma unroll
        for (int rr = 0; rr < 4; rr++) ry[rr] = RYs[lr[rr] * 33 + nt4];

#pragma unroll
        for (int u = 0; u < 4; u++) {
            const int nt = nt4 * 4 + u;
            // ---- QK (split tf32, 3 MMAs per k-step) ----
            float d[2][4] = {{0.f,0.f,0.f,0.f},{0.f,0.f,0.f,0.f}};
#pragma unroll
            for (int s = 0; s < 4; s++) {
                float4 kv = kf[nt * 128 + s * 32];
                u32 kh0 = __float_as_uint(kv.x), kl0 = __float_as_uint(kv.y);
                u32 kh1 = __float_as_uint(kv.z), kl1 = __float_as_uint(kv.w);
#pragma unroll
                for (int mt = 0; mt < 2; mt++) {
                    MMA_TF32(d[mt][0], d[mt][1], d[mt][2], d[mt][3],
                             qh[mt][s][0], qh[mt][s][1], qh[mt][s][2], qh[mt][s][3], kh0, kh1);
                    MMA_TF32(d[mt][0], d[mt][1], d[mt][2], d[mt][3],
                             qh[mt][s][0], qh[mt][s][1], qh[mt][s][2], qh[mt][s][3], kl0, kl1);
                    MMA_TF32(d[mt][0], d[mt][1], d[mt][2], d[mt][3],
                             ql[mt][s][0], ql[mt][s][1], ql[mt][s][2], ql[mt][s][3], kh0, kh1);
                }
            }
            // ---- rel + online softmax ----
            float p[2][4];
#pragma unroll
            for (int mt = 0; mt < 2; mt++) {
                const int rA = mt * 2, rB = rA + 1;
                float s0 = d[mt][0] + rxe[rA][u] + ry[rA];
                float s1 = d[mt][1] + rxo[rA][u] + ry[rA];
                float s2 = d[mt][2] + rxe[rB][u] + ry[rB];
                float s3 = d[mt][3] + rxo[rB][u] + ry[rB];
                float vA = fmaxf(s0, s1), vB = fmaxf(s2, s3);
                vA = fmaxf(vA, __shfl_xor_sync(0xffffffffu, vA, 1));
                vA = fmaxf(vA, __shfl_xor_sync(0xffffffffu, vA, 2));
                vB = fmaxf(vB, __shfl_xor_sync(0xffffffffu, vB, 1));
                vB = fmaxf(vB, __shfl_xor_sync(0xffffffffu, vB, 2));
                if (vA > m[rA]) {
                    float sc = __expf(m[rA] - vA);
                    l[rA] *= sc;
#pragma unroll
                    for (int dt = 0; dt < 4; dt++) { o[mt][dt][0] *= sc; o[mt][dt][1] *= sc; }
                    m[rA] = vA;
                }
                if (vB > m[rB]) {
                    float sc = __expf(m[rB] - vB);
                    l[rB] *= sc;
#pragma unroll
                    for (int dt = 0; dt < 4; dt++) { o[mt][dt][2] *= sc; o[mt][dt][3] *= sc; }
                    m[rB] = vB;
                }
                p[mt][0] = __uint_as_float(tf32_of(__expf(s0 - m[rA])));
                p[mt][1] = __uint_as_float(tf32_of(__expf(s1 - m[rA])));
                p[mt][2] = __uint_as_float(tf32_of(__expf(s2 - m[rB])));
                p[mt][3] = __uint_as_float(tf32_of(__expf(s3 - m[rB])));
                l[rA] += p[mt][0] + p[mt][1];
                l[rB] += p[mt][2] + p[mt][3];
            }
            // ---- P (D-frag) -> A-frag permute within quads ----
            u32 a[2][4];
#pragma unroll
            for (int mt = 0; mt < 2; mt++) {
                float e0 = __shfl_sync(0xffffffffu, p[mt][0], srcA);
                float o0 = __shfl_sync(0xffffffffu, p[mt][1], srcA);
                float e2 = __shfl_sync(0xffffffffu, p[mt][0], srcB);
                float o2 = __shfl_sync(0xffffffffu, p[mt][1], srcB);
                float e1 = __shfl_sync(0xffffffffu, p[mt][2], srcA);
                float o1 = __shfl_sync(0xffffffffu, p[mt][3], srcA);
                float e3 = __shfl_sync(0xffffffffu, p[mt][2], srcB);
                float o3 = __shfl_sync(0xffffffffu, p[mt][3], srcB);
                a[mt][0] = __float_as_uint(sel ? o0 : e0);
                a[mt][1] = __float_as_uint(sel ? o1 : e1);
                a[mt][2] = __float_as_uint(sel ? o2 : e2);
                a[mt][3] = __float_as_uint(sel ? o3 : e3);
            }
            // ---- PV ----
#pragma unroll
            for (int dt = 0; dt < 4; dt++) {
                float2 vv = vf[nt * 128 + dt * 32];
                u32 b0 = __float_as_uint(vv.x), b1 = __float_as_uint(vv.y);
                MMA_TF32(o[0][dt][0], o[0][dt][1], o[0][dt][2], o[0][dt][3],
                         a[0][0], a[0][1], a[0][2], a[0][3], b0, b1);
                MMA_TF32(o[1][dt][0], o[1][dt][1], o[1][dt][2], o[1][dt][3],
                         a[1][0], a[1][1], a[1][2], a[1][3], b0, b1);
            }
        }
    }

    // finalize: reduce l across quad, normalize, write scrambled layout
    float inv[4];
#pragma unroll
    for (int rr = 0; rr < 4; rr++) {
        float lv = l[rr];
        lv += __shfl_xor_sync(0xffffffffu, lv, 1);
        lv += __shfl_xor_sync(0xffffffffu, lv, 2);
        inv[rr] = 1.0f / lv;
    }
    const int b = bh >> 3, h = bh & 7;
#pragma unroll
    for (int mt = 0; mt < 2; mt++)
#pragma unroll
        for (int half = 0; half < 2; half++) {
            int rr = mt * 2 + half;
            int i  = qb + lr[rr];
            float* dst = g_att + (size_t)(b * 256 + h * 32 + (i >> 5)) * 1024
                       + (i & 31) * 32 + 2 * tig;
            float iv = inv[rr];
#pragma unroll
            for (int dt = 0; dt < 4; dt++)
                *(float2*)(dst + dt * 8) =
                    make_float2(o[mt][dt][half * 2] * iv, o[mt][dt][half * 2 + 1] * iv);
        }
}

// ---------------------------------------------------------------------------
// K4: 1x1 projection of attention output -> output channels [256,512)
// ---------------------------------------------------------------------------
__global__ __launch_bounds__(256) void k_proj(const float* __restrict__ aw,
                                              const float* __restrict__ ab,
                                              float* __restrict__ out) {
    __shared__ float As[64 * 68];
    __shared__ float Wt[64 * 65];
    const int bx = blockIdx.x;
    const int b = bx >> 4;
    const int pos0 = (bx & 15) * 64;
    const int co0 = blockIdx.y * 64;
    const int tid = threadIdx.x;
    const int cg = tid >> 4, pg = tid & 15;
    const int col0 = cg * 4, pl0 = pg * 4;

    float acc[4][4] = {};

    for (int cc = 0; cc < 4; cc++) {
        const int ci0 = cc * 64;
        __syncthreads();
        for (int t = tid; t < 1024; t += 256) {
            int rl = t >> 4, f = t & 15;
            *(float4*)&As[rl * 68 + f * 4] =
                *(const float4*)&g_att[(size_t)(b * 256 + ci0 + rl) * 1024 + pos0 + f * 4];
            float4 wv = *(const float4*)&aw[(co0 + rl) * 256 + ci0 + f * 4];
            Wt[(f * 4 + 0) * 65 + rl] = wv.x;
            Wt[(f * 4 + 1) * 65 + rl] = wv.y;
            Wt[(f * 4 + 2) * 65 + rl] = wv.z;
            Wt[(f * 4 + 3) * 65 + rl] = wv.w;
        }
        __syncthreads();
#pragma unroll 8
        for (int k = 0; k < 64; k++) {
            float wv[4], avv[4];
#pragma unroll
            for (int t = 0; t < 4; t++) wv[t]  = Wt[k * 65 + col0 + t];
#pragma unroll
            for (int t = 0; t < 4; t++) avv[t] = As[k * 68 + pl0 + t];
#pragma unroll
            for (int a = 0; a < 4; a++)
#pragma unroll
                for (int p = 0; p < 4; p++) acc[a][p] += wv[a] * avv[p];
        }
    }

#pragma unroll
    for (int a = 0; a < 4; a++) {
        int co = co0 + col0 + a;
        float bb = ab[co];
        *(float4*)&out[(size_t)(b * 512 + 256 + co) * 1024 + pos0 + pl0] =
            make_float4(acc[a][0] + bb, acc[a][1] + bb, acc[a][2] + bb, acc[a][3] + bb);
    }
}

// ---------------------------------------------------------------------------
extern "C" void kernel_launch(void* const* d_in, const int* in_sizes, int n_in,
                              void* d_out, int out_size) {
    const float* x   = (const float*)d_in[0];
    const float* cw  = (const float*)d_in[1];
    const float* cb  = (const float*)d_in[2];
    const float* qw  = (const float*)d_in[3];
    const float* qb  = (const float*)d_in[4];
    const float* aw  = (const float*)d_in[5];
    const float* ab  = (const float*)d_in[6];
    const float* krx = (const float*)d_in[7];
    const float* kry = (const float*)d_in[8];
    float* out = (float*)d_out;

    k_wt  <<<dim3(36, 32), 256>>>(cw, qw);
    k_conv<<<dim3(64, 8), 256>>>(x, cb, qb, out);
    k_rel <<<dim3(32, 32), 256>>>(krx, kry);
    k_prep<<<dim3(32, 8), 256>>>();
    k_attn<<<dim3(32, 8), 128>>>();
    k_proj<<<dim3(64, 4), 256>>>(aw, ab, out);
}

// round 6
// speedup vs baseline: 1.0990x; 1.0990x over previous
#include <cuda_runtime.h>

#define QSCALE 0.17677669529663687f   // 32^-0.5

typedef unsigned long long u64;
typedef unsigned int u32;

// ---------------------------------------------------------------------------
// Scratch (static device arrays; no allocation allowed)
// ---------------------------------------------------------------------------
__device__ __align__(16) float g_wt [1152 * 1024];        // K-major weights [k][co]
__device__ __align__(16) float g_q  [32 * 1024 * 32];     // [bh][pos][d] (scaled)
__device__ __align__(16) float g_k  [32 * 1024 * 32];
__device__ __align__(16) float g_v  [32 * 1024 * 32];
__device__ __align__(16) float g_rx [32 * 1024 * 32];     // [bh][i][jc]
__device__ __align__(16) float g_ry [32 * 1024 * 32];     // [bh][i][jr]
__device__ __align__(16) float g_att[4 * 256 * 1024];     // scrambled-channel att
__device__ __align__(16) float4 g_kf[32 * 128 * 4 * 32];  // split-tf32 K frags (8MB)
__device__ __align__(16) float2 g_vf[32 * 128 * 4 * 32];  // tf32 V frags (4MB)

// ---------------------------------------------------------------------------
// f32x2 packed helpers (conv path)
// ---------------------------------------------------------------------------
__device__ __forceinline__ u64 pk2(float lo, float hi) {
    u64 r; asm("mov.b64 %0,{%1,%2};" : "=l"(r) : "f"(lo), "f"(hi)); return r;
}
__device__ __forceinline__ void upk2(float& lo, float& hi, u64 v) {
    asm("mov.b64 {%0,%1},%2;" : "=f"(lo), "=f"(hi) : "l"(v));
}
__device__ __forceinline__ void ffma2(u64& d, u64 a, u64 b) {
    asm("fma.rn.f32x2 %0,%1,%2,%0;" : "+l"(d) : "l"(a), "l"(b));
}

// ---------------------------------------------------------------------------
// tf32 helpers (attention path)
// ---------------------------------------------------------------------------
__device__ __forceinline__ u32 tf32_of(float f) {
    u32 r; asm("cvt.rna.tf32.f32 %0,%1;" : "=r"(r) : "f"(f)); return r;
}
__device__ __forceinline__ void tf32_split(float v, u32& h, u32& l) {
    h = tf32_of(v);
    l = tf32_of(v - __uint_as_float(h));
}
#define MMA_TF32(d0,d1,d2,d3,a0,a1,a2,a3,b0,b1)                               \
    asm("mma.sync.aligned.m16n8k8.row.col.f32.tf32.tf32.f32 "                  \
        "{%0,%1,%2,%3},{%4,%5,%6,%7},{%8,%9},{%0,%1,%2,%3};"                   \
        : "+f"(d0), "+f"(d1), "+f"(d2), "+f"(d3)                               \
        : "r"(a0), "r"(a1), "r"(a2), "r"(a3), "r"(b0), "r"(b1))

// ---------------------------------------------------------------------------
// K0: tiled coalesced transpose -> K-major [k][co]
// ---------------------------------------------------------------------------
__global__ __launch_bounds__(256) void k_wt(const float* __restrict__ cw,
                                            const float* __restrict__ qw) {
    __shared__ float T[32][33];
    const int tx = threadIdx.x & 31, ty = threadIdx.x >> 5;
    const int k0 = blockIdx.x * 32, c0 = blockIdx.y * 32;
#pragma unroll
    for (int r = 0; r < 4; r++) {
        int co = c0 + ty + r * 8;
        const float* src = (co < 256) ? cw + (size_t)co * 1152
                                      : qw + (size_t)(co - 256) * 1152;
        T[ty + r * 8][tx] = src[k0 + tx];
    }
    __syncthreads();
#pragma unroll
    for (int r = 0; r < 4; r++) {
        int k = k0 + ty + r * 8;
        g_wt[(size_t)k * 1024 + c0 + tx] = T[tx][ty + r * 8];
    }
}

// ---------------------------------------------------------------------------
// K1: fused 3x3 conv. Block: 128 co x 64 pos (2 rows). 256 thr, tile 8co x 4pos.
// ---------------------------------------------------------------------------
__global__ __launch_bounds__(256) void k_conv(const float* __restrict__ x,
                                              const float* __restrict__ cb,
                                              const float* __restrict__ qb,
                                              float* __restrict__ out) {
    __shared__ __align__(16) float Ws[72 * 128];
    __shared__ float Xs[8 * 4 * 37];

    const int tid = threadIdx.x;
    const int b   = blockIdx.x >> 4;
    const int y0  = (blockIdx.x & 15) << 1;
    const int co_base = blockIdx.y << 7;
    const int cg = tid >> 4, pg = tid & 15;
    const int ly = pg >> 3, lx0 = (pg & 7) << 2;
    const int co0 = co_base + cg * 8;

    u64 acc[4][4];
#pragma unroll
    for (int a = 0; a < 4; a++)
#pragma unroll
        for (int c = 0; c < 4; c++) acc[a][c] = 0ULL;

    for (int ch = 0; ch < 16; ch++) {
        const int ci0 = ch << 3;
        __syncthreads();
        for (int t = tid; t < 72 * 32; t += 256) {
            int row = t >> 5, f = t & 31;
            *(float4*)&Ws[row * 128 + f * 4] =
                *(const float4*)&g_wt[(size_t)(ci0 * 9 + row) * 1024 + co_base + f * 4];
        }
        for (int t = tid; t < 1184; t += 256) {
            int ci  = t / 148;
            int rem = t - ci * 148;
            int rr  = rem / 37;
            int c   = rem - rr * 37;
            int gy = y0 - 1 + rr;
            int gx = c - 1;
            float v = 0.f;
            if (gy >= 0 && gy < 32 && (unsigned)gx < 32u)
                v = x[(size_t)((b * 128 + ci0 + ci) * 32 + gy) * 32 + gx];
            Xs[t] = v;
        }
        __syncthreads();
#pragma unroll
        for (int ci = 0; ci < 8; ci++) {
#pragma unroll
            for (int ky = 0; ky < 3; ky++) {
                const float* xp = Xs + ci * 148 + (ly + ky) * 37 + lx0;
                u64 xb[6];
#pragma unroll
                for (int t = 0; t < 6; t++) { float xv = xp[t]; xb[t] = pk2(xv, xv); }
#pragma unroll
                for (int kx = 0; kx < 3; kx++) {
                    const ulonglong2* wp =
                        (const ulonglong2*)(Ws + (ci * 9 + ky * 3 + kx) * 128 + cg * 8);
                    ulonglong2 wA = wp[0], wB = wp[1];
#pragma unroll
                    for (int c = 0; c < 4; c++) {
                        ffma2(acc[0][c], wA.x, xb[kx + c]);
                        ffma2(acc[1][c], wA.y, xb[kx + c]);
                        ffma2(acc[2][c], wB.x, xb[kx + c]);
                        ffma2(acc[3][c], wB.y, xb[kx + c]);
                    }
                }
            }
        }
    }

    float bias[8];
    const float* bsrc = (co0 < 256) ? (cb + co0) : (qb + co0 - 256);
#pragma unroll
    for (int t = 0; t < 8; t++) bias[t] = bsrc[t];

    float v[8][4];
#pragma unroll
    for (int a = 0; a < 4; a++)
#pragma unroll
        for (int c = 0; c < 4; c++) {
            float lo, hi; upk2(lo, hi, acc[a][c]);
            v[2 * a][c]     = lo + bias[2 * a];
            v[2 * a + 1][c] = hi + bias[2 * a + 1];
        }

    const int base_pos = (y0 + ly) * 32 + lx0;
    if (co0 < 256) {
#pragma unroll
        for (int cc = 0; cc < 8; cc++)
            *(float4*)&out[(size_t)(b * 512 + co0 + cc) * 1024 + base_pos] =
                make_float4(v[cc][0], v[cc][1], v[cc][2], v[cc][3]);
    } else {
        int qc0 = co0 - 256;
        int seg = qc0 >> 8;              // 0=q 1=k 2=v
        int c8  = qc0 & 255;
        int h = c8 >> 5, d0 = c8 & 31;
        float* dstb = (seg == 0 ? g_q : (seg == 1 ? g_k : g_v))
                      + (size_t)((b * 8 + h) * 1024) * 32 + d0;
        float scale = (seg == 0) ? QSCALE : 1.f;
#pragma unroll
        for (int c = 0; c < 4; c++) {
            int pos = base_pos + c;
            *(float4*)(dstb + (size_t)pos * 32) =
                make_float4(v[0][c] * scale, v[1][c] * scale, v[2][c] * scale, v[3][c] * scale);
            *(float4*)(dstb + (size_t)pos * 32 + 4) =
                make_float4(v[4][c] * scale, v[5][c] * scale, v[6][c] * scale, v[7][c] * scale);
        }
    }
}

// ---------------------------------------------------------------------------
// K2: rel-logit tables.
// ---------------------------------------------------------------------------
__global__ __launch_bounds__(256) void k_rel(const float* __restrict__ krx,
                                             const float* __restrict__ kry) {
    __shared__ float KX[63 * 33], KY[63 * 33], QR[32 * 32], QT[32 * 32];
    const int bh = blockIdx.x, qg = blockIdx.y, tid = threadIdx.x;

    for (int t = tid; t < 63 * 32; t += 256) {
        int m = t >> 5, d = t & 31;
        KX[m * 33 + d] = krx[t];
        KY[m * 33 + d] = kry[t];
    }
    for (int t = tid; t < 1024; t += 256) {
        int il = t >> 5, d = t & 31;
        QR[t] = g_q[(size_t)(bh * 1024 + qg * 32 + il) * 32 + d];
        QT[t] = g_q[(size_t)(bh * 1024 + il * 32 + qg) * 32 + d];
    }
    __syncthreads();

    const int wid = tid >> 5, j = tid & 31;
#pragma unroll
    for (int r = 0; r < 4; r++) {
        int il = r * 8 + wid;
        int m = j - il + 31;
        float ax = 0.f, ay = 0.f;
#pragma unroll
        for (int d = 0; d < 32; d++) {
            ax += QR[il * 32 + d] * KX[m * 33 + d];
            ay += QT[il * 32 + d] * KY[m * 33 + d];
        }
        int i = qg * 32 + il;
        g_rx[(size_t)(bh * 1024 + i) * 32 + j] = ax;
        g_ry[(size_t)(bh * 1024 + i) * 32 + j] = ay;
    }
}

// ---------------------------------------------------------------------------
// K2b: fragment prep — split-tf32 K frags + tf32 V frags in MMA lane order.
// ---------------------------------------------------------------------------
__global__ __launch_bounds__(256) void k_prep() {
    __shared__ float Ksm[128 * 33], Vsm[128 * 33];
    const int bh = blockIdx.x, c = blockIdx.y, tid = threadIdx.x;
    const int j0 = c * 128;

    for (int t = tid; t < 1024; t += 256) {
        int r = t >> 3, f = (t & 7) * 4;
        float4 kv = *(const float4*)&g_k[(size_t)(bh * 1024 + j0 + r) * 32 + f];
        Ksm[r * 33 + f] = kv.x; Ksm[r * 33 + f + 1] = kv.y;
        Ksm[r * 33 + f + 2] = kv.z; Ksm[r * 33 + f + 3] = kv.w;
        float4 vv = *(const float4*)&g_v[(size_t)(bh * 1024 + j0 + r) * 32 + f];
        Vsm[r * 33 + f] = vv.x; Vsm[r * 33 + f + 1] = vv.y;
        Vsm[r * 33 + f + 2] = vv.z; Vsm[r * 33 + f + 3] = vv.w;
    }
    __syncthreads();

    for (int t = tid; t < 2048; t += 256) {
        int lane = t & 31, s = (t >> 5) & 3, ntl = t >> 7;
        int gid = lane >> 2, tig = lane & 3;
        int j = ntl * 8 + gid;
        u32 h0, l0, h1, l1;
        tf32_split(Ksm[j * 33 + s * 8 + tig],     h0, l0);
        tf32_split(Ksm[j * 33 + s * 8 + tig + 4], h1, l1);
        g_kf[(size_t)((bh * 128 + c * 16 + ntl) * 4 + s) * 32 + lane] =
            make_float4(__uint_as_float(h0), __uint_as_float(l0),
                        __uint_as_float(h1), __uint_as_float(l1));
    }
    for (int t = tid; t < 2048; t += 256) {
        int lane = t & 31, dt = (t >> 5) & 3, ktl = t >> 7;
        int gid = lane >> 2, tig = lane & 3;
        u32 b0 = tf32_of(Vsm[(ktl * 8 + tig) * 33 + dt * 8 + gid]);
        u32 b1 = tf32_of(Vsm[(ktl * 8 + tig + 4) * 33 + dt * 8 + gid]);
        g_vf[(size_t)((bh * 128 + c * 16 + ktl) * 4 + dt) * 32 + lane] =
            make_float2(__uint_as_float(b0), __uint_as_float(b1));
    }
}

// ---------------------------------------------------------------------------
// K3: register-flash tensor-core attention, v4.
// Block = 256 thr = 8 warps: warp w -> q-subtile (w&3) [32 queries],
// key half (w>>2) [512 keys]. NO online max (logits << 88, exp is safe).
// Split-K merge is a pure sum (softmax is linear without max tracking).
// ---------------------------------------------------------------------------
__global__ __launch_bounds__(256) void k_attn() {
    __shared__ float SM[2 * 128 * 33];       // RX | RY, later reused for merge
    float* RXs = SM;
    float* RYs = SM + 128 * 33;

    const int bh = blockIdx.x, qt = blockIdx.y;
    const int tid = threadIdx.x, w = tid >> 5, lane = tid & 31;
    const int wq = w & 3, g = w >> 2;
    const int gid = lane >> 2, tig = lane & 3;
    const int qb = qt * 128;
    const int lq0 = wq * 32;
    const size_t qbase = (size_t)bh * 1024 * 32;

    // stage rel tables for block's 128 queries
    for (int t = tid; t < 128 * 32; t += 256) {
        int r = t >> 5, cc = t & 31;
        RXs[r * 33 + cc] = g_rx[(size_t)(bh * 1024 + qb + r) * 32 + cc];
        RYs[r * 33 + cc] = g_ry[(size_t)(bh * 1024 + qb + r) * 32 + cc];
    }

    // Q fragments (split tf32)
    u32 qh[2][4][4], ql[2][4][4];
#pragma unroll
    for (int mt = 0; mt < 2; mt++)
#pragma unroll
        for (int s = 0; s < 4; s++) {
            int r0 = qb + lq0 + mt * 16 + gid, r1 = r0 + 8;
            int c0 = s * 8 + tig, c1 = c0 + 4;
            tf32_split(g_q[qbase + (size_t)r0 * 32 + c0], qh[mt][s][0], ql[mt][s][0]);
            tf32_split(g_q[qbase + (size_t)r1 * 32 + c0], qh[mt][s][1], ql[mt][s][1]);
            tf32_split(g_q[qbase + (size_t)r0 * 32 + c1], qh[mt][s][2], ql[mt][s][2]);
            tf32_split(g_q[qbase + (size_t)r1 * 32 + c1], qh[mt][s][3], ql[mt][s][3]);
        }
    __syncthreads();

    int lr[4];
#pragma unroll
    for (int rr = 0; rr < 4; rr++) lr[rr] = lq0 + (rr >> 1) * 16 + gid + (rr & 1) * 8;

    float rxe[4][4], rxo[4][4];
#pragma unroll
    for (int rr = 0; rr < 4; rr++)
#pragma unroll
        for (int k = 0; k < 4; k++) {
            rxe[rr][k] = RXs[lr[rr] * 33 + 8 * k + 2 * tig];
            rxo[rr][k] = RXs[lr[rr] * 33 + 8 * k + 2 * tig + 1];
        }

    float l[4] = {0.f, 0.f, 0.f, 0.f};
    float o[2][4][4];
#pragma unroll
    for (int mt = 0; mt < 2; mt++)
#pragma unroll
        for (int dt = 0; dt < 4; dt++)
#pragma unroll
            for (int r = 0; r < 4; r++) o[mt][dt][r] = 0.f;

    const float4* kf = g_kf + (size_t)bh * 16384 + lane;
    const float2* vf = g_vf + (size_t)bh * 16384 + lane;
    const int srcA = (lane & ~3) | (tig >> 1);
    const int srcB = srcA + 2;
    const int sel  = tig & 1;

    for (int nt4 = g * 16; nt4 < g * 16 + 16; nt4++) {
        float ry[4];
#pragma unroll
        for (int rr = 0; rr < 4; rr++) ry[rr] = RYs[lr[rr] * 33 + nt4];

#pragma unroll
        for (int u = 0; u < 4; u++) {
            const int nt = nt4 * 4 + u;
            // ---- QK (split tf32, 3 MMAs per k-step) ----
            float d[2][4] = {{0.f,0.f,0.f,0.f},{0.f,0.f,0.f,0.f}};
#pragma unroll
            for (int s = 0; s < 4; s++) {
                float4 kv = kf[nt * 128 + s * 32];
                u32 kh0 = __float_as_uint(kv.x), kl0 = __float_as_uint(kv.y);
                u32 kh1 = __float_as_uint(kv.z), kl1 = __float_as_uint(kv.w);
#pragma unroll
                for (int mt = 0; mt < 2; mt++) {
                    MMA_TF32(d[mt][0], d[mt][1], d[mt][2], d[mt][3],
                             qh[mt][s][0], qh[mt][s][1], qh[mt][s][2], qh[mt][s][3], kh0, kh1);
                    MMA_TF32(d[mt][0], d[mt][1], d[mt][2], d[mt][3],
                             qh[mt][s][0], qh[mt][s][1], qh[mt][s][2], qh[mt][s][3], kl0, kl1);
                    MMA_TF32(d[mt][0], d[mt][1], d[mt][2], d[mt][3],
                             ql[mt][s][0], ql[mt][s][1], ql[mt][s][2], ql[mt][s][3], kh0, kh1);
                }
            }
            // ---- rel + exp (no max subtraction needed: |logits| << 88) ----
            float p[2][4];
#pragma unroll
            for (int mt = 0; mt < 2; mt++) {
                const int rA = mt * 2, rB = rA + 1;
                p[mt][0] = __uint_as_float(tf32_of(__expf(d[mt][0] + rxe[rA][u] + ry[rA])));
                p[mt][1] = __uint_as_float(tf32_of(__expf(d[mt][1] + rxo[rA][u] + ry[rA])));
                p[mt][2] = __uint_as_float(tf32_of(__expf(d[mt][2] + rxe[rB][u] + ry[rB])));
                p[mt][3] = __uint_as_float(tf32_of(__expf(d[mt][3] + rxo[rB][u] + ry[rB])));
                l[rA] += p[mt][0] + p[mt][1];
                l[rB] += p[mt][2] + p[mt][3];
            }
            // ---- P (D-frag) -> A-frag permute within quads ----
            u32 a[2][4];
#pragma unroll
            for (int mt = 0; mt < 2; mt++) {
                float e0 = __shfl_sync(0xffffffffu, p[mt][0], srcA);
                float o0 = __shfl_sync(0xffffffffu, p[mt][1], srcA);
                float e2 = __shfl_sync(0xffffffffu, p[mt][0], srcB);
                float o2 = __shfl_sync(0xffffffffu, p[mt][1], srcB);
                float e1 = __shfl_sync(0xffffffffu, p[mt][2], srcA);
                float o1 = __shfl_sync(0xffffffffu, p[mt][3], srcA);
                float e3 = __shfl_sync(0xffffffffu, p[mt][2], srcB);
                float o3 = __shfl_sync(0xffffffffu, p[mt][3], srcB);
                a[mt][0] = __float_as_uint(sel ? o0 : e0);
                a[mt][1] = __float_as_uint(sel ? o1 : e1);
                a[mt][2] = __float_as_uint(sel ? o2 : e2);
                a[mt][3] = __float_as_uint(sel ? o3 : e3);
            }
            // ---- PV ----
#pragma unroll
            for (int dt = 0; dt < 4; dt++) {
                float2 vv = vf[nt * 128 + dt * 32];
                u32 b0 = __float_as_uint(vv.x), b1 = __float_as_uint(vv.y);
                MMA_TF32(o[0][dt][0], o[0][dt][1], o[0][dt][2], o[0][dt][3],
                         a[0][0], a[0][1], a[0][2], a[0][3], b0, b1);
                MMA_TF32(o[1][dt][0], o[1][dt][1], o[1][dt][2], o[1][dt][3],
                         a[1][0], a[1][1], a[1][2], a[1][3], b0, b1);
            }
        }
    }

    // ---- split-K merge: pure sums (no max state). Reuse SM region. ----
    __syncthreads();
    float* MO = SM;                       // [wq*32+lane][33]
    float* ML = SM + 128 * 33;            // [wq*32+lane][4]
    if (g == 1) {
        float* mo = MO + (wq * 32 + lane) * 33;
#pragma unroll
        for (int mt = 0; mt < 2; mt++)
#pragma unroll
            for (int dt = 0; dt < 4; dt++)
#pragma unroll
                for (int r = 0; r < 4; r++) mo[mt * 16 + dt * 4 + r] = o[mt][dt][r];
        float* ml = ML + (wq * 32 + lane) * 4;
#pragma unroll
        for (int rr = 0; rr < 4; rr++) ml[rr] = l[rr];
    }
    __syncthreads();
    if (g == 0) {
        const float* mo = MO + (wq * 32 + lane) * 33;
#pragma unroll
        for (int mt = 0; mt < 2; mt++)
#pragma unroll
            for (int dt = 0; dt < 4; dt++)
#pragma unroll
                for (int r = 0; r < 4; r++) o[mt][dt][r] += mo[mt * 16 + dt * 4 + r];
        const float* ml = ML + (wq * 32 + lane) * 4;
#pragma unroll
        for (int rr = 0; rr < 4; rr++) l[rr] += ml[rr];

        float inv[4];
#pragma unroll
        for (int rr = 0; rr < 4; rr++) {
            float lv = l[rr];
            lv += __shfl_xor_sync(0xffffffffu, lv, 1);
            lv += __shfl_xor_sync(0xffffffffu, lv, 2);
            inv[rr] = 1.0f / lv;
        }
        const int b = bh >> 3, h = bh & 7;
#pragma unroll
        for (int mt = 0; mt < 2; mt++)
#pragma unroll
            for (int half = 0; half < 2; half++) {
                int rr = mt * 2 + half;
                int i  = qb + lr[rr];
                float* dst = g_att + (size_t)(b * 256 + h * 32 + (i >> 5)) * 1024
                           + (i & 31) * 32 + 2 * tig;
                float iv = inv[rr];
#pragma unroll
                for (int dt = 0; dt < 4; dt++)
                    *(float2*)(dst + dt * 8) =
                        make_float2(o[mt][dt][half * 2] * iv, o[mt][dt][half * 2 + 1] * iv);
            }
    }
}

// ---------------------------------------------------------------------------
// K4: 1x1 projection of attention output -> output channels [256,512)
// ---------------------------------------------------------------------------
__global__ __launch_bounds__(256) void k_proj(const float* __restrict__ aw,
                                              const float* __restrict__ ab,
                                              float* __restrict__ out) {
    __shared__ float As[64 * 68];
    __shared__ float Wt[64 * 65];
    const int bx = blockIdx.x;
    const int b = bx >> 4;
    const int pos0 = (bx & 15) * 64;
    const int co0 = blockIdx.y * 64;
    const int tid = threadIdx.x;
    const int cg = tid >> 4, pg = tid & 15;
    const int col0 = cg * 4, pl0 = pg * 4;

    float acc[4][4] = {};

    for (int cc = 0; cc < 4; cc++) {
        const int ci0 = cc * 64;
        __syncthreads();
        for (int t = tid; t < 1024; t += 256) {
            int rl = t >> 4, f = t & 15;
            *(float4*)&As[rl * 68 + f * 4] =
                *(const float4*)&g_att[(size_t)(b * 256 + ci0 + rl) * 1024 + pos0 + f * 4];
            float4 wv = *(const float4*)&aw[(co0 + rl) * 256 + ci0 + f * 4];
            Wt[(f * 4 + 0) * 65 + rl] = wv.x;
            Wt[(f * 4 + 1) * 65 + rl] = wv.y;
            Wt[(f * 4 + 2) * 65 + rl] = wv.z;
            Wt[(f * 4 + 3) * 65 + rl] = wv.w;
        }
        __syncthreads();
#pragma unroll 8
        for (int k = 0; k < 64; k++) {
            float wv[4], avv[4];
#pragma unroll
            for (int t = 0; t < 4; t++) wv[t]  = Wt[k * 65 + col0 + t];
#pragma unroll
            for (int t = 0; t < 4; t++) avv[t] = As[k * 68 + pl0 + t];
#pragma unroll
            for (int a = 0; a < 4; a++)
#pragma unroll
                for (int p = 0; p < 4; p++) acc[a][p] += wv[a] * avv[p];
        }
    }

#pragma unroll
    for (int a = 0; a < 4; a++) {
        int co = co0 + col0 + a;
        float bb = ab[co];
        *(float4*)&out[(size_t)(b * 512 + 256 + co) * 1024 + pos0 + pl0] =
            make_float4(acc[a][0] + bb, acc[a][1] + bb, acc[a][2] + bb, acc[a][3] + bb);
    }
}

// ---------------------------------------------------------------------------
extern "C" void kernel_launch(void* const* d_in, const int* in_sizes, int n_in,
                              void* d_out, int out_size) {
    const float* x   = (const float*)d_in[0];
    const float* cw  = (const float*)d_in[1];
    const float* cb  = (const float*)d_in[2];
    const float* qw  = (const float*)d_in[3];
    const float* qb  = (const float*)d_in[4];
    const float* aw  = (const float*)d_in[5];
    const float* ab  = (const float*)d_in[6];
    const float* krx = (const float*)d_in[7];
    const float* kry = (const float*)d_in[8];
    float* out = (float*)d_out;

    k_wt  <<<dim3(36, 32), 256>>>(cw, qw);
    k_conv<<<dim3(64, 8), 256>>>(x, cb, qb, out);
    k_rel <<<dim3(32, 32), 256>>>(krx, kry);
    k_prep<<<dim3(32, 8), 256>>>();
    k_attn<<<dim3(32, 8), 256>>>();
    k_proj<<<dim3(64, 4), 256>>>(aw, ab, out);
}

// round 7
// speedup vs baseline: 1.4339x; 1.3047x over previous
#include <cuda_runtime.h>
#include <cuda_bf16.h>

#define QSCALE 0.17677669529663687f   // 32^-0.5

typedef unsigned long long u64;
typedef unsigned int u32;

// ---------------------------------------------------------------------------
// Scratch (static device arrays; no allocation allowed)
// ---------------------------------------------------------------------------
__device__ __align__(16) float g_q  [32 * 1024 * 32];     // [bh][pos][d] (scaled)
__device__ __align__(16) float g_k  [32 * 1024 * 32];
__device__ __align__(16) float g_v  [32 * 1024 * 32];
__device__ __align__(16) float g_rx [32 * 1024 * 32];     // [bh][i][jc]
__device__ __align__(16) float g_ry [32 * 1024 * 32];     // [bh][i][jr]
__device__ __align__(16) float g_att[4 * 256 * 1024];     // scrambled-channel att
__device__ __align__(16) float4 g_kf[32 * 128 * 4 * 32];  // split-tf32 K frags
__device__ __align__(16) float2 g_vf[32 * 128 * 4 * 32];  // tf32 V frags
__device__ __align__(16) uint4 g_xf_hi[256 * 72 * 32];    // im2col A frags (bf16 hi)
__device__ __align__(16) uint4 g_xf_lo[256 * 72 * 32];    // im2col A frags (bf16 lo)
__device__ __align__(16) uint4 g_wf   [72 * 128 * 32];    // weight B frags (hi,hi,lo,lo)

// ---------------------------------------------------------------------------
// bf16 helpers (conv path)
// ---------------------------------------------------------------------------
__device__ __forceinline__ u32 bpack(__nv_bfloat16 a, __nv_bfloat16 b) {
    return (u32)__bfloat16_as_ushort(a) | ((u32)__bfloat16_as_ushort(b) << 16);
}
__device__ __forceinline__ void bsplit2(float v0, float v1, u32& hi, u32& lo) {
    __nv_bfloat16 h0 = __float2bfloat16_rn(v0), h1 = __float2bfloat16_rn(v1);
    __nv_bfloat16 l0 = __float2bfloat16_rn(v0 - __bfloat162float(h0));
    __nv_bfloat16 l1 = __float2bfloat16_rn(v1 - __bfloat162float(h1));
    hi = bpack(h0, h1); lo = bpack(l0, l1);
}
#define MMA_BF16(d0,d1,d2,d3,a0,a1,a2,a3,b0,b1)                                \
    asm("mma.sync.aligned.m16n8k16.row.col.f32.bf16.bf16.f32 "                  \
        "{%0,%1,%2,%3},{%4,%5,%6,%7},{%8,%9},{%0,%1,%2,%3};"                    \
        : "+f"(d0), "+f"(d1), "+f"(d2), "+f"(d3)                                \
        : "r"(a0), "r"(a1), "r"(a2), "r"(a3), "r"(b0), "r"(b1))

__device__ __forceinline__ void cp16(u32 saddr, const void* g) {
    asm volatile("cp.async.cg.shared.global [%0], [%1], 16;" :: "r"(saddr), "l"(g));
}
#define CP_COMMIT() asm volatile("cp.async.commit_group;")
#define CP_WAIT0()  asm volatile("cp.async.wait_group 0;")

// ---------------------------------------------------------------------------
// tf32 helpers (attention path)
// ---------------------------------------------------------------------------
__device__ __forceinline__ u32 tf32_of(float f) {
    u32 r; asm("cvt.rna.tf32.f32 %0,%1;" : "=r"(r) : "f"(f)); return r;
}
__device__ __forceinline__ void tf32_split(float v, u32& h, u32& l) {
    h = tf32_of(v);
    l = tf32_of(v - __uint_as_float(h));
}
#define MMA_TF32(d0,d1,d2,d3,a0,a1,a2,a3,b0,b1)                                \
    asm("mma.sync.aligned.m16n8k8.row.col.f32.tf32.tf32.f32 "                   \
        "{%0,%1,%2,%3},{%4,%5,%6,%7},{%8,%9},{%0,%1,%2,%3};"                    \
        : "+f"(d0), "+f"(d1), "+f"(d2), "+f"(d3)                                \
        : "r"(a0), "r"(a1), "r"(a2), "r"(a3), "r"(b0), "r"(b1))

// ---------------------------------------------------------------------------
// K_xf: im2col -> split-bf16 A fragments in MMA lane order.
// Block handles 16 positions (pt), all 72 ksteps. pos = b*1024 + y*32 + x.
// A[r][k] = x[b][ci][y+ky-1][x0+r+kx-1],  k = ci*9 + ky*3 + kx.
// ---------------------------------------------------------------------------
__global__ __launch_bounds__(256) void k_xf(const float* __restrict__ x) {
    __shared__ float Xs[128][3][20];
    const int pt = blockIdx.x, tid = threadIdx.x;
    const int pos0 = pt * 16;
    const int b = pos0 >> 10, y = (pos0 >> 5) & 31, x0 = pos0 & 31;

    for (int t = tid; t < 128 * 54; t += 256) {
        int ci = t / 54, rem = t - ci * 54;
        int ky = rem / 18, cc = rem - ky * 18;
        int gy = y + ky - 1, gx = x0 - 1 + cc;
        float v = 0.f;
        if ((unsigned)gy < 32u && (unsigned)gx < 32u)
            v = x[(size_t)((b * 128 + ci) * 32 + gy) * 32 + gx];
        Xs[ci][ky][cc] = v;
    }
    __syncthreads();

    for (int u = tid; u < 72 * 32; u += 256) {
        int ks = u >> 5, lane = u & 31;
        int gid = lane >> 2, tig = lane & 3;
        int r0 = gid, r1 = gid + 8;
        u32 hi[4], lo[4];
#pragma unroll
        for (int half = 0; half < 2; half++) {
            int k0 = ks * 16 + 2 * tig + half * 8;
            int k1 = k0 + 1;
            int ci0 = k0 / 9, tp0 = k0 - ci0 * 9;
            int ci1 = k1 / 9, tp1 = k1 - ci1 * 9;
            int ky0 = tp0 / 3, kx0 = tp0 - ky0 * 3;
            int ky1 = tp1 / 3, kx1 = tp1 - ky1 * 3;
            float A00 = Xs[ci0][ky0][r0 + kx0];
            float A01 = Xs[ci1][ky1][r0 + kx1];
            float A10 = Xs[ci0][ky0][r1 + kx0];
            float A11 = Xs[ci1][ky1][r1 + kx1];
            bsplit2(A00, A01, hi[half * 2],     lo[half * 2]);
            bsplit2(A10, A11, hi[half * 2 + 1], lo[half * 2 + 1]);
        }
        size_t idx = ((size_t)pt * 72 + ks) * 32 + lane;
        g_xf_hi[idx] = make_uint4(hi[0], hi[1], hi[2], hi[3]);
        g_xf_lo[idx] = make_uint4(lo[0], lo[1], lo[2], lo[3]);
    }
}

// ---------------------------------------------------------------------------
// K_wf: weights -> split-bf16 B fragments. B[k][co], co<256 from cw else qw.
// Grid (8 co-tiles of 128, 8 kstep-groups of 9).
// ---------------------------------------------------------------------------
__global__ __launch_bounds__(256) void k_wf(const float* __restrict__ cw,
                                            const float* __restrict__ qw) {
    __shared__ float W[16][132];
    const int ct = blockIdx.x, ks0 = blockIdx.y * 9, tid = threadIdx.x;
    for (int ks = ks0; ks < ks0 + 9; ks++) {
        __syncthreads();
        for (int t = tid; t < 2048; t += 256) {
            int kl = t & 15, col = t >> 4;
            int co = ct * 128 + col;
            const float* src = (co < 256) ? cw + (size_t)co * 1152
                                          : qw + (size_t)(co - 256) * 1152;
            W[kl][col] = src[ks * 16 + kl];
        }
        __syncthreads();
        for (int u = tid; u < 512; u += 256) {
            int ntl = u >> 5, lane = u & 31, gid = lane >> 2, tig = lane & 3;
            int col = ntl * 8 + gid;
            u32 b0h, b0l, b1h, b1l;
            bsplit2(W[2 * tig][col],     W[2 * tig + 1][col], b0h, b0l);
            bsplit2(W[2 * tig + 8][col], W[2 * tig + 9][col], b1h, b1l);
            g_wf[((size_t)ks * 128 + ct * 16 + ntl) * 32 + lane] =
                make_uint4(b0h, b1h, b0l, b1l);
        }
    }
}

// ---------------------------------------------------------------------------
// K_gemm: fused conv as bf16-split tensor-core GEMM (4096 x 1024 x 1152).
// Grid (128 pos-tiles of 32, 4 co-quarters). Block 256 thr = 2 m-parts x 4 n-parts.
// by: 0 -> conv_out (direct to out), 1/2/3 -> q/k/v scratch.
// ---------------------------------------------------------------------------
__global__ __launch_bounds__(256) void k_gemm(const float* __restrict__ cb,
                                              const float* __restrict__ qb,
                                              float* __restrict__ out) {
    __shared__ __align__(16) uint4 Bs[2][1024];   // 32 ntiles x 32 lanes, double buf
    const int tid = threadIdx.x, w = tid >> 5, lane = tid & 31;
    const int gid = lane >> 2, tig = lane & 3;
    const int mpart = w & 1, npart = w >> 1;
    const int pt = blockIdx.x * 2 + mpart;
    const int by = blockIdx.y;

    float c[8][4];
#pragma unroll
    for (int nt = 0; nt < 8; nt++)
#pragma unroll
        for (int r = 0; r < 4; r++) c[nt][r] = 0.f;

    const u32 sbase = (u32)__cvta_generic_to_shared(Bs);

    {   // prefetch ks=0
        const uint4* src = g_wf + ((size_t)0 * 128 + by * 32) * 32;
#pragma unroll
        for (int i = 0; i < 4; i++) {
            int idx = tid + i * 256;
            cp16(sbase + idx * 16, src + idx);
        }
        CP_COMMIT(); CP_WAIT0();
    }
    __syncthreads();

    for (int ks = 0; ks < 72; ks++) {
        const int buf = ks & 1;
        if (ks < 71) {
            const uint4* src = g_wf + ((size_t)(ks + 1) * 128 + by * 32) * 32;
#pragma unroll
            for (int i = 0; i < 4; i++) {
                int idx = tid + i * 256;
                cp16(sbase + (buf ^ 1) * 16384 + idx * 16, src + idx);
            }
            CP_COMMIT();
        }
        uint4 ah = g_xf_hi[((size_t)pt * 72 + ks) * 32 + lane];
        uint4 al = g_xf_lo[((size_t)pt * 72 + ks) * 32 + lane];
#pragma unroll
        for (int nt = 0; nt < 8; nt++) {
            uint4 bb = Bs[buf][(npart * 8 + nt) * 32 + lane];
            MMA_BF16(c[nt][0], c[nt][1], c[nt][2], c[nt][3],
                     ah.x, ah.y, ah.z, ah.w, bb.x, bb.y);
            MMA_BF16(c[nt][0], c[nt][1], c[nt][2], c[nt][3],
                     ah.x, ah.y, ah.z, ah.w, bb.z, bb.w);
            MMA_BF16(c[nt][0], c[nt][1], c[nt][2], c[nt][3],
                     al.x, al.y, al.z, al.w, bb.x, bb.y);
        }
        if (ks < 71) { CP_WAIT0(); }
        __syncthreads();
    }

    // epilogue
    const int r0g = pt * 16 + gid, r1g = r0g + 8;
    const int b = r0g >> 10;
    const int p0 = r0g & 1023, p1 = r1g & 1023;
    if (by == 0) {
#pragma unroll
        for (int nt = 0; nt < 8; nt++) {
            int co = npart * 64 + nt * 8 + 2 * tig;
            float bb0 = cb[co], bb1 = cb[co + 1];
            float* o0 = out + (size_t)(b * 512 + co) * 1024;
            o0[p0] = c[nt][0] + bb0;
            o0[p1] = c[nt][2] + bb0;
            o0 += 1024;
            o0[p0] = c[nt][1] + bb1;
            o0[p1] = c[nt][3] + bb1;
        }
    } else {
        const int seg = by - 1;                       // 0=q 1=k 2=v
        float* base = seg == 0 ? g_q : (seg == 1 ? g_k : g_v);
        const float scale = (seg == 0) ? QSCALE : 1.f;
#pragma unroll
        for (int nt = 0; nt < 8; nt++) {
            int c8 = npart * 64 + nt * 8 + 2 * tig;
            int qc = seg * 256 + c8;
            int h = c8 >> 5, d0 = c8 & 31;
            float bb0 = qb[qc], bb1 = qb[qc + 1];
            float* dst = base + (size_t)((b * 8 + h) * 1024) * 32 + d0;
            *(float2*)(dst + (size_t)p0 * 32) =
                make_float2((c[nt][0] + bb0) * scale, (c[nt][1] + bb1) * scale);
            *(float2*)(dst + (size_t)p1 * 32) =
                make_float2((c[nt][2] + bb0) * scale, (c[nt][3] + bb1) * scale);
        }
    }
}

// ---------------------------------------------------------------------------
// K2: rel-logit tables.
// ---------------------------------------------------------------------------
__global__ __launch_bounds__(256) void k_rel(const float* __restrict__ krx,
                                             const float* __restrict__ kry) {
    __shared__ float KX[63 * 33], KY[63 * 33], QR[32 * 32], QT[32 * 32];
    const int bh = blockIdx.x, qg = blockIdx.y, tid = threadIdx.x;

    for (int t = tid; t < 63 * 32; t += 256) {
        int m = t >> 5, d = t & 31;
        KX[m * 33 + d] = krx[t];
        KY[m * 33 + d] = kry[t];
    }
    for (int t = tid; t < 1024; t += 256) {
        int il = t >> 5, d = t & 31;
        QR[t] = g_q[(size_t)(bh * 1024 + qg * 32 + il) * 32 + d];
        QT[t] = g_q[(size_t)(bh * 1024 + il * 32 + qg) * 32 + d];
    }
    __syncthreads();

    const int wid = tid >> 5, j = tid & 31;
#pragma unroll
    for (int r = 0; r < 4; r++) {
        int il = r * 8 + wid;
        int m = j - il + 31;
        float ax = 0.f, ay = 0.f;
#pragma unroll
        for (int d = 0; d < 32; d++) {
            ax += QR[il * 32 + d] * KX[m * 33 + d];
            ay += QT[il * 32 + d] * KY[m * 33 + d];
        }
        int i = qg * 32 + il;
        g_rx[(size_t)(bh * 1024 + i) * 32 + j] = ax;
        g_ry[(size_t)(bh * 1024 + i) * 32 + j] = ay;
    }
}

// ---------------------------------------------------------------------------
// K2b: fragment prep — split-tf32 K frags + tf32 V frags in MMA lane order.
// ---------------------------------------------------------------------------
__global__ __launch_bounds__(256) void k_prep() {
    __shared__ float Ksm[128 * 33], Vsm[128 * 33];
    const int bh = blockIdx.x, c = blockIdx.y, tid = threadIdx.x;
    const int j0 = c * 128;

    for (int t = tid; t < 1024; t += 256) {
        int r = t >> 3, f = (t & 7) * 4;
        float4 kv = *(const float4*)&g_k[(size_t)(bh * 1024 + j0 + r) * 32 + f];
        Ksm[r * 33 + f] = kv.x; Ksm[r * 33 + f + 1] = kv.y;
        Ksm[r * 33 + f + 2] = kv.z; Ksm[r * 33 + f + 3] = kv.w;
        float4 vv = *(const float4*)&g_v[(size_t)(bh * 1024 + j0 + r) * 32 + f];
        Vsm[r * 33 + f] = vv.x; Vsm[r * 33 + f + 1] = vv.y;
        Vsm[r * 33 + f + 2] = vv.z; Vsm[r * 33 + f + 3] = vv.w;
    }
    __syncthreads();

    for (int t = tid; t < 2048; t += 256) {
        int lane = t & 31, s = (t >> 5) & 3, ntl = t >> 7;
        int gid = lane >> 2, tig = lane & 3;
        int j = ntl * 8 + gid;
        u32 h0, l0, h1, l1;
        tf32_split(Ksm[j * 33 + s * 8 + tig],     h0, l0);
        tf32_split(Ksm[j * 33 + s * 8 + tig + 4], h1, l1);
        g_kf[(size_t)((bh * 128 + c * 16 + ntl) * 4 + s) * 32 + lane] =
            make_float4(__uint_as_float(h0), __uint_as_float(l0),
                        __uint_as_float(h1), __uint_as_float(l1));
    }
    for (int t = tid; t < 2048; t += 256) {
        int lane = t & 31, dt = (t >> 5) & 3, ktl = t >> 7;
        int gid = lane >> 2, tig = lane & 3;
        u32 b0 = tf32_of(Vsm[(ktl * 8 + tig) * 33 + dt * 8 + gid]);
        u32 b1 = tf32_of(Vsm[(ktl * 8 + tig + 4) * 33 + dt * 8 + gid]);
        g_vf[(size_t)((bh * 128 + c * 16 + ktl) * 4 + dt) * 32 + lane] =
            make_float2(__uint_as_float(b0), __uint_as_float(b1));
    }
}

// ---------------------------------------------------------------------------
// K3: register-flash tensor-core attention, v4 (no max; logits << 88).
// ---------------------------------------------------------------------------
__global__ __launch_bounds__(256) void k_attn() {
    __shared__ float SM[2 * 128 * 33];
    float* RXs = SM;
    float* RYs = SM + 128 * 33;

    const int bh = blockIdx.x, qt = blockIdx.y;
    const int tid = threadIdx.x, w = tid >> 5, lane = tid & 31;
    const int wq = w & 3, g = w >> 2;
    const int gid = lane >> 2, tig = lane & 3;
    const int qb = qt * 128;
    const int lq0 = wq * 32;
    const size_t qbase = (size_t)bh * 1024 * 32;

    for (int t = tid; t < 128 * 32; t += 256) {
        int r = t >> 5, cc = t & 31;
        RXs[r * 33 + cc] = g_rx[(size_t)(bh * 1024 + qb + r) * 32 + cc];
        RYs[r * 33 + cc] = g_ry[(size_t)(bh * 1024 + qb + r) * 32 + cc];
    }

    u32 qh[2][4][4], ql[2][4][4];
#pragma unroll
    for (int mt = 0; mt < 2; mt++)
#pragma unroll
        for (int s = 0; s < 4; s++) {
            int r0 = qb + lq0 + mt * 16 + gid, r1 = r0 + 8;
            int c0 = s * 8 + tig, c1 = c0 + 4;
            tf32_split(g_q[qbase + (size_t)r0 * 32 + c0], qh[mt][s][0], ql[mt][s][0]);
            tf32_split(g_q[qbase + (size_t)r1 * 32 + c0], qh[mt][s][1], ql[mt][s][1]);
            tf32_split(g_q[qbase + (size_t)r0 * 32 + c1], qh[mt][s][2], ql[mt][s][2]);
            tf32_split(g_q[qbase + (size_t)r1 * 32 + c1], qh[mt][s][3], ql[mt][s][3]);
        }
    __syncthreads();

    int lr[4];
#pragma unroll
    for (int rr = 0; rr < 4; rr++) lr[rr] = lq0 + (rr >> 1) * 16 + gid + (rr & 1) * 8;

    float rxe[4][4], rxo[4][4];
#pragma unroll
    for (int rr = 0; rr < 4; rr++)
#pragma unroll
        for (int k = 0; k < 4; k++) {
            rxe[rr][k] = RXs[lr[rr] * 33 + 8 * k + 2 * tig];
            rxo[rr][k] = RXs[lr[rr] * 33 + 8 * k + 2 * tig + 1];
        }

    float l[4] = {0.f, 0.f, 0.f, 0.f};
    float o[2][4][4];
#pragma unroll
    for (int mt = 0; mt < 2; mt++)
#pragma unroll
        for (int dt = 0; dt < 4; dt++)
#pragma unroll
            for (int r = 0; r < 4; r++) o[mt][dt][r] = 0.f;

    const float4* kf = g_kf + (size_t)bh * 16384 + lane;
    const float2* vf = g_vf + (size_t)bh * 16384 + lane;
    const int srcA = (lane & ~3) | (tig >> 1);
    const int srcB = srcA + 2;
    const int sel  = tig & 1;

    for (int nt4 = g * 16; nt4 < g * 16 + 16; nt4++) {
        float ry[4];
#pragma unroll
        for (int rr = 0; rr < 4; rr++) ry[rr] = RYs[lr[rr] * 33 + nt4];

#pragma unroll
        for (int u = 0; u < 4; u++) {
            const int nt = nt4 * 4 + u;
            float d[2][4] = {{0.f,0.f,0.f,0.f},{0.f,0.f,0.f,0.f}};
#pragma unroll
            for (int s = 0; s < 4; s++) {
                float4 kv = kf[nt * 128 + s * 32];
                u32 kh0 = __float_as_uint(kv.x), kl0 = __float_as_uint(kv.y);
                u32 kh1 = __float_as_uint(kv.z), kl1 = __float_as_uint(kv.w);
#pragma unroll
                for (int mt = 0; mt < 2; mt++) {
                    MMA_TF32(d[mt][0], d[mt][1], d[mt][2], d[mt][3],
                             qh[mt][s][0], qh[mt][s][1], qh[mt][s][2], qh[mt][s][3], kh0, kh1);
                    MMA_TF32(d[mt][0], d[mt][1], d[mt][2], d[mt][3],
                             qh[mt][s][0], qh[mt][s][1], qh[mt][s][2], qh[mt][s][3], kl0, kl1);
                    MMA_TF32(d[mt][0], d[mt][1], d[mt][2], d[mt][3],
                             ql[mt][s][0], ql[mt][s][1], ql[mt][s][2], ql[mt][s][3], kh0, kh1);
                }
            }
            float p[2][4];
#pragma unroll
            for (int mt = 0; mt < 2; mt++) {
                const int rA = mt * 2, rB = rA + 1;
                p[mt][0] = __uint_as_float(tf32_of(__expf(d[mt][0] + rxe[rA][u] + ry[rA])));
                p[mt][1] = __uint_as_float(tf32_of(__expf(d[mt][1] + rxo[rA][u] + ry[rA])));
                p[mt][2] = __uint_as_float(tf32_of(__expf(d[mt][2] + rxe[rB][u] + ry[rB])));
                p[mt][3] = __uint_as_float(tf32_of(__expf(d[mt][3] + rxo[rB][u] + ry[rB])));
                l[rA] += p[mt][0] + p[mt][1];
                l[rB] += p[mt][2] + p[mt][3];
            }
            u32 a[2][4];
#pragma unroll
            for (int mt = 0; mt < 2; mt++) {
                float e0 = __shfl_sync(0xffffffffu, p[mt][0], srcA);
                float o0 = __shfl_sync(0xffffffffu, p[mt][1], srcA);
                float e2 = __shfl_sync(0xffffffffu, p[mt][0], srcB);
                float o2 = __shfl_sync(0xffffffffu, p[mt][1], srcB);
                float e1 = __shfl_sync(0xffffffffu, p[mt][2], srcA);
                float o1 = __shfl_sync(0xffffffffu, p[mt][3], srcA);
                float e3 = __shfl_sync(0xffffffffu, p[mt][2], srcB);
                float o3 = __shfl_sync(0xffffffffu, p[mt][3], srcB);
                a[mt][0] = __float_as_uint(sel ? o0 : e0);
                a[mt][1] = __float_as_uint(sel ? o1 : e1);
                a[mt][2] = __float_as_uint(sel ? o2 : e2);
                a[mt][3] = __float_as_uint(sel ? o3 : e3);
            }
#pragma unroll
            for (int dt = 0; dt < 4; dt++) {
                float2 vv = vf[nt * 128 + dt * 32];
                u32 b0 = __float_as_uint(vv.x), b1 = __float_as_uint(vv.y);
                MMA_TF32(o[0][dt][0], o[0][dt][1], o[0][dt][2], o[0][dt][3],
                         a[0][0], a[0][1], a[0][2], a[0][3], b0, b1);
                MMA_TF32(o[1][dt][0], o[1][dt][1], o[1][dt][2], o[1][dt][3],
                         a[1][0], a[1][1], a[1][2], a[1][3], b0, b1);
            }
        }
    }

    __syncthreads();
    float* MO = SM;
    float* ML = SM + 128 * 33;
    if (g == 1) {
        float* mo = MO + (wq * 32 + lane) * 33;
#pragma unroll
        for (int mt = 0; mt < 2; mt++)
#pragma unroll
            for (int dt = 0; dt < 4; dt++)
#pragma unroll
                for (int r = 0; r < 4; r++) mo[mt * 16 + dt * 4 + r] = o[mt][dt][r];
        float* ml = ML + (wq * 32 + lane) * 4;
#pragma unroll
        for (int rr = 0; rr < 4; rr++) ml[rr] = l[rr];
    }
    __syncthreads();
    if (g == 0) {
        const float* mo = MO + (wq * 32 + lane) * 33;
#pragma unroll
        for (int mt = 0; mt < 2; mt++)
#pragma unroll
            for (int dt = 0; dt < 4; dt++)
#pragma unroll
                for (int r = 0; r < 4; r++) o[mt][dt][r] += mo[mt * 16 + dt * 4 + r];
        const float* ml = ML + (wq * 32 + lane) * 4;
#pragma unroll
        for (int rr = 0; rr < 4; rr++) l[rr] += ml[rr];

        float inv[4];
#pragma unroll
        for (int rr = 0; rr < 4; rr++) {
            float lv = l[rr];
            lv += __shfl_xor_sync(0xffffffffu, lv, 1);
            lv += __shfl_xor_sync(0xffffffffu, lv, 2);
            inv[rr] = 1.0f / lv;
        }
        const int b = bh >> 3, h = bh & 7;
#pragma unroll
        for (int mt = 0; mt < 2; mt++)
#pragma unroll
            for (int half = 0; half < 2; half++) {
                int rr = mt * 2 + half;
                int i  = qb + lr[rr];
                float* dst = g_att + (size_t)(b * 256 + h * 32 + (i >> 5)) * 1024
                           + (i & 31) * 32 + 2 * tig;
                float iv = inv[rr];
#pragma unroll
                for (int dt = 0; dt < 4; dt++)
                    *(float2*)(dst + dt * 8) =
                        make_float2(o[mt][dt][half * 2] * iv, o[mt][dt][half * 2 + 1] * iv);
            }
    }
}

// ---------------------------------------------------------------------------
// K4: 1x1 projection of attention output -> output channels [256,512)
// ---------------------------------------------------------------------------
__global__ __launch_bounds__(256) void k_proj(const float* __restrict__ aw,
                                              const float* __restrict__ ab,
                                              float* __restrict__ out) {
    __shared__ float As[64 * 68];
    __shared__ float Wt[64 * 65];
    const int bx = blockIdx.x;
    const int b = bx >> 4;
    const int pos0 = (bx & 15) * 64;
    const int co0 = blockIdx.y * 64;
    const int tid = threadIdx.x;
    const int cg = tid >> 4, pg = tid & 15;
    const int col0 = cg * 4, pl0 = pg * 4;

    float acc[4][4] = {};

    for (int cc = 0; cc < 4; cc++) {
        const int ci0 = cc * 64;
        __syncthreads();
        for (int t = tid; t < 1024; t += 256) {
            int rl = t >> 4, f = t & 15;
            *(float4*)&As[rl * 68 + f * 4] =
                *(const float4*)&g_att[(size_t)(b * 256 + ci0 + rl) * 1024 + pos0 + f * 4];
            float4 wv = *(const float4*)&aw[(co0 + rl) * 256 + ci0 + f * 4];
            Wt[(f * 4 + 0) * 65 + rl] = wv.x;
            Wt[(f * 4 + 1) * 65 + rl] = wv.y;
            Wt[(f * 4 + 2) * 65 + rl] = wv.z;
            Wt[(f * 4 + 3) * 65 + rl] = wv.w;
        }
        __syncthreads();
#pragma unroll 8
        for (int k = 0; k < 64; k++) {
            float wv[4], avv[4];
#pragma unroll
            for (int t = 0; t < 4; t++) wv[t]  = Wt[k * 65 + col0 + t];
#pragma unroll
            for (int t = 0; t < 4; t++) avv[t] = As[k * 68 + pl0 + t];
#pragma unroll
            for (int a = 0; a < 4; a++)
#pragma unroll
                for (int p = 0; p < 4; p++) acc[a][p] += wv[a] * avv[p];
        }
    }

#pragma unroll
    for (int a = 0; a < 4; a++) {
        int co = co0 + col0 + a;
        float bb = ab[co];
        *(float4*)&out[(size_t)(b * 512 + 256 + co) * 1024 + pos0 + pl0] =
            make_float4(acc[a][0] + bb, acc[a][1] + bb, acc[a][2] + bb, acc[a][3] + bb);
    }
}

// ---------------------------------------------------------------------------
extern "C" void kernel_launch(void* const* d_in, const int* in_sizes, int n_in,
                              void* d_out, int out_size) {
    const float* x   = (const float*)d_in[0];
    const float* cw  = (const float*)d_in[1];
    const float* cb  = (const float*)d_in[2];
    const float* qw  = (const float*)d_in[3];
    const float* qb  = (const float*)d_in[4];
    const float* aw  = (const float*)d_in[5];
    const float* ab  = (const float*)d_in[6];
    const float* krx = (const float*)d_in[7];
    const float* kry = (const float*)d_in[8];
    float* out = (float*)d_out;

    k_xf  <<<256, 256>>>(x);
    k_wf  <<<dim3(8, 8), 256>>>(cw, qw);
    k_gemm<<<dim3(128, 4), 256>>>(cb, qb, out);
    k_rel <<<dim3(32, 32), 256>>>(krx, kry);
    k_prep<<<dim3(32, 8), 256>>>();
    k_attn<<<dim3(32, 8), 256>>>();
    k_proj<<<dim3(64, 4), 256>>>(aw, ab, out);
}

// round 8
// speedup vs baseline: 2.1629x; 1.5084x over previous
#include <cuda_runtime.h>
#include <cuda_bf16.h>

#define QSCALE 0.17677669529663687f   // 32^-0.5

typedef unsigned long long u64;
typedef unsigned int u32;

// ---------------------------------------------------------------------------
// Scratch (static device arrays; no allocation allowed)
// ---------------------------------------------------------------------------
__device__ __align__(16) float g_q  [32 * 1024 * 32];     // [bh][pos][d] (scaled)
__device__ __align__(16) float g_k  [32 * 1024 * 32];
__device__ __align__(16) float g_v  [32 * 1024 * 32];
__device__ __align__(16) float g_rx [32 * 1024 * 32];     // [bh][i][jc]
__device__ __align__(16) float g_ry [32 * 1024 * 32];     // [bh][i][jr]
__device__ __align__(16) float g_att[4 * 256 * 1024];     // scrambled-channel att
__device__ __align__(16) uint4  g_kbf[32 * 128 * 2 * 32]; // split-bf16 K B-frags (4MB)
__device__ __align__(16) float2 g_vf[32 * 128 * 4 * 32];  // tf32 V frags
__device__ __align__(16) uint4 g_xf_hi[256 * 72 * 32];    // im2col A frags (bf16 hi)
__device__ __align__(16) uint4 g_xf_lo[256 * 72 * 32];    // im2col A frags (bf16 lo)
__device__ __align__(16) uint4 g_wf   [72 * 128 * 32];    // weight B frags (hi,hi,lo,lo)

// ---------------------------------------------------------------------------
// bf16 helpers
// ---------------------------------------------------------------------------
__device__ __forceinline__ u32 bpack(__nv_bfloat16 a, __nv_bfloat16 b) {
    return (u32)__bfloat16_as_ushort(a) | ((u32)__bfloat16_as_ushort(b) << 16);
}
__device__ __forceinline__ void bsplit2(float v0, float v1, u32& hi, u32& lo) {
    __nv_bfloat16 h0 = __float2bfloat16_rn(v0), h1 = __float2bfloat16_rn(v1);
    __nv_bfloat16 l0 = __float2bfloat16_rn(v0 - __bfloat162float(h0));
    __nv_bfloat16 l1 = __float2bfloat16_rn(v1 - __bfloat162float(h1));
    hi = bpack(h0, h1); lo = bpack(l0, l1);
}
#define MMA_BF16(d0,d1,d2,d3,a0,a1,a2,a3,b0,b1)                                \
    asm("mma.sync.aligned.m16n8k16.row.col.f32.bf16.bf16.f32 "                  \
        "{%0,%1,%2,%3},{%4,%5,%6,%7},{%8,%9},{%0,%1,%2,%3};"                    \
        : "+f"(d0), "+f"(d1), "+f"(d2), "+f"(d3)                                \
        : "r"(a0), "r"(a1), "r"(a2), "r"(a3), "r"(b0), "r"(b1))

__device__ __forceinline__ void cp16(u32 saddr, const void* g) {
    asm volatile("cp.async.cg.shared.global [%0], [%1], 16;" :: "r"(saddr), "l"(g));
}
#define CP_COMMIT() asm volatile("cp.async.commit_group;")
#define CP_WAIT0()  asm volatile("cp.async.wait_group 0;")

// ---------------------------------------------------------------------------
// tf32 helpers
// ---------------------------------------------------------------------------
__device__ __forceinline__ u32 tf32_of(float f) {
    u32 r; asm("cvt.rna.tf32.f32 %0,%1;" : "=r"(r) : "f"(f)); return r;
}
#define MMA_TF32(d0,d1,d2,d3,a0,a1,a2,a3,b0,b1)                                \
    asm("mma.sync.aligned.m16n8k8.row.col.f32.tf32.tf32.f32 "                   \
        "{%0,%1,%2,%3},{%4,%5,%6,%7},{%8,%9},{%0,%1,%2,%3};"                    \
        : "+f"(d0), "+f"(d1), "+f"(d2), "+f"(d3)                                \
        : "r"(a0), "r"(a1), "r"(a2), "r"(a3), "r"(b0), "r"(b1))

// ---------------------------------------------------------------------------
// K_xf: im2col -> split-bf16 A fragments in MMA lane order.
// ---------------------------------------------------------------------------
__global__ __launch_bounds__(256) void k_xf(const float* __restrict__ x) {
    __shared__ float Xs[128][3][20];
    const int pt = blockIdx.x, tid = threadIdx.x;
    const int pos0 = pt * 16;
    const int b = pos0 >> 10, y = (pos0 >> 5) & 31, x0 = pos0 & 31;

    for (int t = tid; t < 128 * 54; t += 256) {
        int ci = t / 54, rem = t - ci * 54;
        int ky = rem / 18, cc = rem - ky * 18;
        int gy = y + ky - 1, gx = x0 - 1 + cc;
        float v = 0.f;
        if ((unsigned)gy < 32u && (unsigned)gx < 32u)
            v = x[(size_t)((b * 128 + ci) * 32 + gy) * 32 + gx];
        Xs[ci][ky][cc] = v;
    }
    __syncthreads();

    for (int u = tid; u < 72 * 32; u += 256) {
        int ks = u >> 5, lane = u & 31;
        int gid = lane >> 2, tig = lane & 3;
        int r0 = gid, r1 = gid + 8;
        u32 hi[4], lo[4];
#pragma unroll
        for (int half = 0; half < 2; half++) {
            int k0 = ks * 16 + 2 * tig + half * 8;
            int k1 = k0 + 1;
            int ci0 = k0 / 9, tp0 = k0 - ci0 * 9;
            int ci1 = k1 / 9, tp1 = k1 - ci1 * 9;
            int ky0 = tp0 / 3, kx0 = tp0 - ky0 * 3;
            int ky1 = tp1 / 3, kx1 = tp1 - ky1 * 3;
            float A00 = Xs[ci0][ky0][r0 + kx0];
            float A01 = Xs[ci1][ky1][r0 + kx1];
            float A10 = Xs[ci0][ky0][r1 + kx0];
            float A11 = Xs[ci1][ky1][r1 + kx1];
            bsplit2(A00, A01, hi[half * 2],     lo[half * 2]);
            bsplit2(A10, A11, hi[half * 2 + 1], lo[half * 2 + 1]);
        }
        size_t idx = ((size_t)pt * 72 + ks) * 32 + lane;
        g_xf_hi[idx] = make_uint4(hi[0], hi[1], hi[2], hi[3]);
        g_xf_lo[idx] = make_uint4(lo[0], lo[1], lo[2], lo[3]);
    }
}

// ---------------------------------------------------------------------------
// K_wf: weights -> split-bf16 B fragments.
// ---------------------------------------------------------------------------
__global__ __launch_bounds__(256) void k_wf(const float* __restrict__ cw,
                                            const float* __restrict__ qw) {
    __shared__ float W[16][132];
    const int ct = blockIdx.x, ks0 = blockIdx.y * 9, tid = threadIdx.x;
    for (int ks = ks0; ks < ks0 + 9; ks++) {
        __syncthreads();
        for (int t = tid; t < 2048; t += 256) {
            int kl = t & 15, col = t >> 4;
            int co = ct * 128 + col;
            const float* src = (co < 256) ? cw + (size_t)co * 1152
                                          : qw + (size_t)(co - 256) * 1152;
            W[kl][col] = src[ks * 16 + kl];
        }
        __syncthreads();
        for (int u = tid; u < 512; u += 256) {
            int ntl = u >> 5, lane = u & 31, gid = lane >> 2, tig = lane & 3;
            int col = ntl * 8 + gid;
            u32 b0h, b0l, b1h, b1l;
            bsplit2(W[2 * tig][col],     W[2 * tig + 1][col], b0h, b0l);
            bsplit2(W[2 * tig + 8][col], W[2 * tig + 9][col], b1h, b1l);
            g_wf[((size_t)ks * 128 + ct * 16 + ntl) * 32 + lane] =
                make_uint4(b0h, b1h, b0l, b1l);
        }
    }
}

// ---------------------------------------------------------------------------
// K_gemm: fused conv as bf16-split tensor-core GEMM (4096 x 1024 x 1152).
// ---------------------------------------------------------------------------
__global__ __launch_bounds__(256) void k_gemm(const float* __restrict__ cb,
                                              const float* __restrict__ qb,
                                              float* __restrict__ out) {
    __shared__ __align__(16) uint4 Bs[2][1024];
    const int tid = threadIdx.x, w = tid >> 5, lane = tid & 31;
    const int gid = lane >> 2, tig = lane & 3;
    const int mpart = w & 1, npart = w >> 1;
    const int pt = blockIdx.x * 2 + mpart;
    const int by = blockIdx.y;

    float c[8][4];
#pragma unroll
    for (int nt = 0; nt < 8; nt++)
#pragma unroll
        for (int r = 0; r < 4; r++) c[nt][r] = 0.f;

    const u32 sbase = (u32)__cvta_generic_to_shared(Bs);

    {
        const uint4* src = g_wf + ((size_t)0 * 128 + by * 32) * 32;
#pragma unroll
        for (int i = 0; i < 4; i++) {
            int idx = tid + i * 256;
            cp16(sbase + idx * 16, src + idx);
        }
        CP_COMMIT(); CP_WAIT0();
    }
    __syncthreads();

    for (int ks = 0; ks < 72; ks++) {
        const int buf = ks & 1;
        if (ks < 71) {
            const uint4* src = g_wf + ((size_t)(ks + 1) * 128 + by * 32) * 32;
#pragma unroll
            for (int i = 0; i < 4; i++) {
                int idx = tid + i * 256;
                cp16(sbase + (buf ^ 1) * 16384 + idx * 16, src + idx);
            }
            CP_COMMIT();
        }
        uint4 ah = g_xf_hi[((size_t)pt * 72 + ks) * 32 + lane];
        uint4 al = g_xf_lo[((size_t)pt * 72 + ks) * 32 + lane];
#pragma unroll
        for (int nt = 0; nt < 8; nt++) {
            uint4 bb = Bs[buf][(npart * 8 + nt) * 32 + lane];
            MMA_BF16(c[nt][0], c[nt][1], c[nt][2], c[nt][3],
                     ah.x, ah.y, ah.z, ah.w, bb.x, bb.y);
            MMA_BF16(c[nt][0], c[nt][1], c[nt][2], c[nt][3],
                     ah.x, ah.y, ah.z, ah.w, bb.z, bb.w);
            MMA_BF16(c[nt][0], c[nt][1], c[nt][2], c[nt][3],
                     al.x, al.y, al.z, al.w, bb.x, bb.y);
        }
        if (ks < 71) { CP_WAIT0(); }
        __syncthreads();
    }

    const int r0g = pt * 16 + gid, r1g = r0g + 8;
    const int b = r0g >> 10;
    const int p0 = r0g & 1023, p1 = r1g & 1023;
    if (by == 0) {
#pragma unroll
        for (int nt = 0; nt < 8; nt++) {
            int co = npart * 64 + nt * 8 + 2 * tig;
            float bb0 = cb[co], bb1 = cb[co + 1];
            float* o0 = out + (size_t)(b * 512 + co) * 1024;
            o0[p0] = c[nt][0] + bb0;
            o0[p1] = c[nt][2] + bb0;
            o0 += 1024;
            o0[p0] = c[nt][1] + bb1;
            o0[p1] = c[nt][3] + bb1;
        }
    } else {
        const int seg = by - 1;
        float* base = seg == 0 ? g_q : (seg == 1 ? g_k : g_v);
        const float scale = (seg == 0) ? QSCALE : 1.f;
#pragma unroll
        for (int nt = 0; nt < 8; nt++) {
            int c8 = npart * 64 + nt * 8 + 2 * tig;
            int qc = seg * 256 + c8;
            int h = c8 >> 5, d0 = c8 & 31;
            float bb0 = qb[qc], bb1 = qb[qc + 1];
            float* dst = base + (size_t)((b * 8 + h) * 1024) * 32 + d0;
            *(float2*)(dst + (size_t)p0 * 32) =
                make_float2((c[nt][0] + bb0) * scale, (c[nt][1] + bb1) * scale);
            *(float2*)(dst + (size_t)p1 * 32) =
                make_float2((c[nt][2] + bb0) * scale, (c[nt][3] + bb1) * scale);
        }
    }
}

// ---------------------------------------------------------------------------
// K2: rel-logit tables.
// ---------------------------------------------------------------------------
__global__ __launch_bounds__(256) void k_rel(const float* __restrict__ krx,
                                             const float* __restrict__ kry) {
    __shared__ float KX[63 * 33], KY[63 * 33], QR[32 * 32], QT[32 * 32];
    const int bh = blockIdx.x, qg = blockIdx.y, tid = threadIdx.x;

    for (int t = tid; t < 63 * 32; t += 256) {
        int m = t >> 5, d = t & 31;
        KX[m * 33 + d] = krx[t];
        KY[m * 33 + d] = kry[t];
    }
    for (int t = tid; t < 1024; t += 256) {
        int il = t >> 5, d = t & 31;
        QR[t] = g_q[(size_t)(bh * 1024 + qg * 32 + il) * 32 + d];
        QT[t] = g_q[(size_t)(bh * 1024 + il * 32 + qg) * 32 + d];
    }
    __syncthreads();

    const int wid = tid >> 5, j = tid & 31;
#pragma unroll
    for (int r = 0; r < 4; r++) {
        int il = r * 8 + wid;
        int m = j - il + 31;
        float ax = 0.f, ay = 0.f;
#pragma unroll
        for (int d = 0; d < 32; d++) {
            ax += QR[il * 32 + d] * KX[m * 33 + d];
            ay += QT[il * 32 + d] * KY[m * 33 + d];
        }
        int i = qg * 32 + il;
        g_rx[(size_t)(bh * 1024 + i) * 32 + j] = ax;
        g_ry[(size_t)(bh * 1024 + i) * 32 + j] = ay;
    }
}

// ---------------------------------------------------------------------------
// K2b: fragment prep — split-bf16 K B-frags (k16) + tf32 V frags.
//   g_kbf[((bh*128+nt)*2+s)*32+lane] = {b0h,b1h,b0l,b1l},
//     b0 = K[nt*8+gid][16s+2tig], [.. +1]; b1 = +8 cols.
// ---------------------------------------------------------------------------
__global__ __launch_bounds__(256) void k_prep() {
    __shared__ float Ksm[128 * 33], Vsm[128 * 33];
    const int bh = blockIdx.x, c = blockIdx.y, tid = threadIdx.x;
    const int j0 = c * 128;

    for (int t = tid; t < 1024; t += 256) {
        int r = t >> 3, f = (t & 7) * 4;
        float4 kv = *(const float4*)&g_k[(size_t)(bh * 1024 + j0 + r) * 32 + f];
        Ksm[r * 33 + f] = kv.x; Ksm[r * 33 + f + 1] = kv.y;
        Ksm[r * 33 + f + 2] = kv.z; Ksm[r * 33 + f + 3] = kv.w;
        float4 vv = *(const float4*)&g_v[(size_t)(bh * 1024 + j0 + r) * 32 + f];
        Vsm[r * 33 + f] = vv.x; Vsm[r * 33 + f + 1] = vv.y;
        Vsm[r * 33 + f + 2] = vv.z; Vsm[r * 33 + f + 3] = vv.w;
    }
    __syncthreads();

    for (int t = tid; t < 1024; t += 256) {
        int lane = t & 31, s = (t >> 5) & 1, ntl = t >> 6;
        int gid = lane >> 2, tig = lane & 3;
        int j = ntl * 8 + gid;
        int k0 = s * 16 + 2 * tig;
        u32 b0h, b0l, b1h, b1l;
        bsplit2(Ksm[j * 33 + k0],     Ksm[j * 33 + k0 + 1], b0h, b0l);
        bsplit2(Ksm[j * 33 + k0 + 8], Ksm[j * 33 + k0 + 9], b1h, b1l);
        g_kbf[(size_t)((bh * 128 + c * 16 + ntl) * 2 + s) * 32 + lane] =
            make_uint4(b0h, b1h, b0l, b1l);
    }
    for (int t = tid; t < 2048; t += 256) {
        int lane = t & 31, dt = (t >> 5) & 3, ktl = t >> 7;
        int gid = lane >> 2, tig = lane & 3;
        u32 b0 = tf32_of(Vsm[(ktl * 8 + tig) * 33 + dt * 8 + gid]);
        u32 b1 = tf32_of(Vsm[(ktl * 8 + tig + 4) * 33 + dt * 8 + gid]);
        g_vf[(size_t)((bh * 128 + c * 16 + ktl) * 4 + dt) * 32 + lane] =
            make_float2(__uint_as_float(b0), __uint_as_float(b1));
    }
}

// ---------------------------------------------------------------------------
// K3: register-flash tensor-core attention, v5.
// Block 256 thr = 8 warps; warp owns 16 queries, streams ALL 1024 keys
// (128 tiles of 8). QK via split-bf16 m16n8k16 (6 MMAs/tile, 2 acc chains);
// PV via tf32 k8. No max subtraction, no split-K merge.
// ---------------------------------------------------------------------------
__global__ void __launch_bounds__(256, 2) k_attn() {
    __shared__ float RXs[128 * 33], RYs[128 * 33];

    const int bh = blockIdx.x, qt = blockIdx.y;
    const int tid = threadIdx.x, w = tid >> 5, lane = tid & 31;
    const int gid = lane >> 2, tig = lane & 3;
    const int qb = qt * 128;
    const int lq = w * 16;
    const size_t qbase = (size_t)bh * 1024 * 32;

    for (int t = tid; t < 128 * 32; t += 256) {
        int r = t >> 5, cc = t & 31;
        RXs[r * 33 + cc] = g_rx[(size_t)(bh * 1024 + qb + r) * 32 + cc];
        RYs[r * 33 + cc] = g_ry[(size_t)(bh * 1024 + qb + r) * 32 + cc];
    }

    // Q fragments, split-bf16, m16n8k16 A layout
    u32 qh[2][4], ql[2][4];
    {
        const float* q0 = g_q + qbase + (size_t)(qb + lq + gid) * 32;
        const float* q1 = q0 + 8 * 32;
#pragma unroll
        for (int s = 0; s < 2; s++) {
            int k0 = s * 16 + 2 * tig;
            bsplit2(q0[k0],     q0[k0 + 1], qh[s][0], ql[s][0]);
            bsplit2(q1[k0],     q1[k0 + 1], qh[s][1], ql[s][1]);
            bsplit2(q0[k0 + 8], q0[k0 + 9], qh[s][2], ql[s][2]);
            bsplit2(q1[k0 + 8], q1[k0 + 9], qh[s][3], ql[s][3]);
        }
    }
    __syncthreads();

    const int lrA = lq + gid, lrB = lrA + 8;

    float rxe[2][4], rxo[2][4];
#pragma unroll
    for (int k = 0; k < 4; k++) {
        rxe[0][k] = RXs[lrA * 33 + 8 * k + 2 * tig];
        rxo[0][k] = RXs[lrA * 33 + 8 * k + 2 * tig + 1];
        rxe[1][k] = RXs[lrB * 33 + 8 * k + 2 * tig];
        rxo[1][k] = RXs[lrB * 33 + 8 * k + 2 * tig + 1];
    }

    float l0 = 0.f, l1 = 0.f;
    float o[4][4];
#pragma unroll
    for (int dt = 0; dt < 4; dt++)
#pragma unroll
        for (int r = 0; r < 4; r++) o[dt][r] = 0.f;

    const uint4*  kf = g_kbf + (size_t)bh * 8192 + lane;
    const float2* vf = g_vf + (size_t)bh * 16384 + lane;
    const int srcA = (lane & ~3) | (tig >> 1);
    const int srcB = srcA + 2;
    const int sel  = tig & 1;

    for (int nt4 = 0; nt4 < 32; nt4++) {
        const float ryA = RYs[lrA * 33 + nt4];
        const float ryB = RYs[lrB * 33 + nt4];

#pragma unroll
        for (int u = 0; u < 4; u++) {
            const int nt = nt4 * 4 + u;
            // ---- QK: split-bf16, two independent accumulator chains ----
            float dh[4] = {0.f, 0.f, 0.f, 0.f};
            float dx[4] = {0.f, 0.f, 0.f, 0.f};
#pragma unroll
            for (int s = 0; s < 2; s++) {
                uint4 kb = kf[(nt * 2 + s) * 32];
                MMA_BF16(dh[0], dh[1], dh[2], dh[3],
                         qh[s][0], qh[s][1], qh[s][2], qh[s][3], kb.x, kb.y);
                MMA_BF16(dx[0], dx[1], dx[2], dx[3],
                         qh[s][0], qh[s][1], qh[s][2], qh[s][3], kb.z, kb.w);
                MMA_BF16(dx[0], dx[1], dx[2], dx[3],
                         ql[s][0], ql[s][1], ql[s][2], ql[s][3], kb.x, kb.y);
            }
            // ---- rel + exp (no max; |logits| << 88) ----
            float p0 = __uint_as_float(tf32_of(__expf(dh[0] + dx[0] + rxe[0][u] + ryA)));
            float p1 = __uint_as_float(tf32_of(__expf(dh[1] + dx[1] + rxo[0][u] + ryA)));
            float p2 = __uint_as_float(tf32_of(__expf(dh[2] + dx[2] + rxe[1][u] + ryB)));
            float p3 = __uint_as_float(tf32_of(__expf(dh[3] + dx[3] + rxo[1][u] + ryB)));
            l0 += p0 + p1;
            l1 += p2 + p3;
            // ---- D-frag -> A-frag permute within quads ----
            float e0 = __shfl_sync(0xffffffffu, p0, srcA);
            float o0 = __shfl_sync(0xffffffffu, p1, srcA);
            float e2 = __shfl_sync(0xffffffffu, p0, srcB);
            float o2 = __shfl_sync(0xffffffffu, p1, srcB);
            float e1 = __shfl_sync(0xffffffffu, p2, srcA);
            float o1 = __shfl_sync(0xffffffffu, p3, srcA);
            float e3 = __shfl_sync(0xffffffffu, p2, srcB);
            float o3 = __shfl_sync(0xffffffffu, p3, srcB);
            u32 a0 = __float_as_uint(sel ? o0 : e0);
            u32 a1 = __float_as_uint(sel ? o1 : e1);
            u32 a2 = __float_as_uint(sel ? o2 : e2);
            u32 a3 = __float_as_uint(sel ? o3 : e3);
            // ---- PV (tf32 k8) ----
#pragma unroll
            for (int dt = 0; dt < 4; dt++) {
                float2 vv = vf[(nt * 4 + dt) * 32];
                u32 b0 = __float_as_uint(vv.x), b1 = __float_as_uint(vv.y);
                MMA_TF32(o[dt][0], o[dt][1], o[dt][2], o[dt][3],
                         a0, a1, a2, a3, b0, b1);
            }
        }
    }

    // finalize: quad-reduce l, normalize, write scrambled layout
    l0 += __shfl_xor_sync(0xffffffffu, l0, 1);
    l0 += __shfl_xor_sync(0xffffffffu, l0, 2);
    l1 += __shfl_xor_sync(0xffffffffu, l1, 1);
    l1 += __shfl_xor_sync(0xffffffffu, l1, 2);
    const float inv0 = 1.0f / l0, inv1 = 1.0f / l1;

    const int b = bh >> 3, h = bh & 7;
    {
        int i = qb + lrA;
        float* dst = g_att + (size_t)(b * 256 + h * 32 + (i >> 5)) * 1024
                   + (i & 31) * 32 + 2 * tig;
#pragma unroll
        for (int dt = 0; dt < 4; dt++)
            *(float2*)(dst + dt * 8) = make_float2(o[dt][0] * inv0, o[dt][1] * inv0);
    }
    {
        int i = qb + lrB;
        float* dst = g_att + (size_t)(b * 256 + h * 32 + (i >> 5)) * 1024
                   + (i & 31) * 32 + 2 * tig;
#pragma unroll
        for (int dt = 0; dt < 4; dt++)
            *(float2*)(dst + dt * 8) = make_float2(o[dt][2] * inv1, o[dt][3] * inv1);
    }
}

// ---------------------------------------------------------------------------
// K4: 1x1 projection of attention output -> output channels [256,512)
// ---------------------------------------------------------------------------
__global__ __launch_bounds__(256) void k_proj(const float* __restrict__ aw,
                                              const float* __restrict__ ab,
                                              float* __restrict__ out) {
    __shared__ float As[64 * 68];
    __shared__ float Wt[64 * 65];
    const int bx = blockIdx.x;
    const int b = bx >> 4;
    const int pos0 = (bx & 15) * 64;
    const int co0 = blockIdx.y * 64;
    const int tid = threadIdx.x;
    const int cg = tid >> 4, pg = tid & 15;
    const int col0 = cg * 4, pl0 = pg * 4;

    float acc[4][4] = {};

    for (int cc = 0; cc < 4; cc++) {
        const int ci0 = cc * 64;
        __syncthreads();
        for (int t = tid; t < 1024; t += 256) {
            int rl = t >> 4, f = t & 15;
            *(float4*)&As[rl * 68 + f * 4] =
                *(const float4*)&g_att[(size_t)(b * 256 + ci0 + rl) * 1024 + pos0 + f * 4];
            float4 wv = *(const float4*)&aw[(co0 + rl) * 256 + ci0 + f * 4];
            Wt[(f * 4 + 0) * 65 + rl] = wv.x;
            Wt[(f * 4 + 1) * 65 + rl] = wv.y;
            Wt[(f * 4 + 2) * 65 + rl] = wv.z;
            Wt[(f * 4 + 3) * 65 + rl] = wv.w;
        }
        __syncthreads();
#pragma unroll 8
        for (int k = 0; k < 64; k++) {
            float wv[4], avv[4];
#pragma unroll
            for (int t = 0; t < 4; t++) wv[t]  = Wt[k * 65 + col0 + t];
#pragma unroll
            for (int t = 0; t < 4; t++) avv[t] = As[k * 68 + pl0 + t];
#pragma unroll
            for (int a = 0; a < 4; a++)
#pragma unroll
                for (int p = 0; p < 4; p++) acc[a][p] += wv[a] * avv[p];
        }
    }

#pragma unroll
    for (int a = 0; a < 4; a++) {
        int co = co0 + col0 + a;
        float bb = ab[co];
        *(float4*)&out[(size_t)(b * 512 + 256 + co) * 1024 + pos0 + pl0] =
            make_float4(acc[a][0] + bb, acc[a][1] + bb, acc[a][2] + bb, acc[a][3] + bb);
    }
}

// ---------------------------------------------------------------------------
extern "C" void kernel_launch(void* const* d_in, const int* in_sizes, int n_in,
                              void* d_out, int out_size) {
    const float* x   = (const float*)d_in[0];
    const float* cw  = (const float*)d_in[1];
    const float* cb  = (const float*)d_in[2];
    const float* qw  = (const float*)d_in[3];
    const float* qb  = (const float*)d_in[4];
    const float* aw  = (const float*)d_in[5];
    const float* ab  = (const float*)d_in[6];
    const float* krx = (const float*)d_in[7];
    const float* kry = (const float*)d_in[8];
    float* out = (float*)d_out;

    k_xf  <<<256, 256>>>(x);
    k_wf  <<<dim3(8, 8), 256>>>(cw, qw);
    k_gemm<<<dim3(128, 4), 256>>>(cb, qb, out);
    k_rel <<<dim3(32, 32), 256>>>(krx, kry);
    k_prep<<<dim3(32, 8), 256>>>();
    k_attn<<<dim3(32, 8), 256>>>();
    k_proj<<<dim3(64, 4), 256>>>(aw, ab, out);
}